// round 15
// baseline (speedup 1.0000x reference)
#include <cuda_runtime.h>
#include <cuda_bf16.h>
#include <cuda_fp16.h>
#include <math.h>
#include <stdint.h>

// Problem constants
#define Bn 2
#define Cn 192
#define Hn 256
#define Wn 256
#define HWn 65536
#define NHn 6
#define HDn 32
#define RAD 10
#define NT  21            // 2*RAD+1 taps
#define BCHW (2*192*65536)
#define QSCALE 0.17677669529663689f

// ---------------- scratch (device globals; no runtime allocation) -------------
__device__ __half   g_hp[BCHW];           // highpass magnitude (= prompt), fp16
__device__ uint32_t g_xpk[2*96*65536];    // LN output, paired bf16 [b][k2][p]
__device__ uint32_t g_qk[2*192*65536];    // Q pairs (0..95) K pairs (96..191), per batch
__device__ __half   g_v[BCHW];            // V fp16 [b][c][p]
__device__ float    g_sum[BCHW];          // dwconv + attention output (fp32)
__device__ float    g_smmean[Bn*HWn];
__device__ float    g_smmax [Bn*HWn];
__device__ float    g_w2    [Bn*HWn];
__device__ float    g_lpsum[Bn*Cn];
__device__ unsigned g_lpmax[Bn*Cn];
__device__ float    g_w1[Bn*Cn];
__device__ float    g_s1r[256];           // 1D spatial kernel (real part)
__device__ float    g_sak[2*49];          // combined 7x7 spatial-attn kernel
__device__ float    g_biasT[NHn*64*64];   // rel-pos bias table
__device__ uint32_t g_apk[96*640];        // qkv weights paired-bf16 [k2][o] (Q pre-scaled)
__device__ uint32_t g_ppk[96*256];        // proj weights paired-bf16 [k2][o]
__device__ float    g_qkvb[3*Cn];         // (Q bias pre-scaled)

__device__ __forceinline__ uint32_t packbf(float lo, float hi) {
    __nv_bfloat162 h = __floats2bfloat162_rn(lo, hi);
    return *(uint32_t*)&h;
}

__device__ __forceinline__ void mma_bf16(float* d, const uint32_t* a, const uint32_t* b) {
    asm volatile("mma.sync.aligned.m16n8k16.row.col.f32.bf16.bf16.f32 "
        "{%0,%1,%2,%3}, {%4,%5,%6,%7}, {%8,%9}, {%0,%1,%2,%3};"
        : "+f"(d[0]), "+f"(d[1]), "+f"(d[2]), "+f"(d[3])
        : "r"(a[0]), "r"(a[1]), "r"(a[2]), "r"(a[3]), "r"(b[0]), "r"(b[1]));
}

// ---------------- setup: s1 kernel + combined SA kernel + zero stats ----------
__global__ void k_setup(const float* __restrict__ sa3, const float* __restrict__ sa5,
                        const float* __restrict__ sa7) {
    int n = threadIdx.x;  // 256 threads
    float re = 0.f;
    const float inv2c2 = 1.0f / (2.0f * 25.6f * 25.6f);
    for (int k = 0; k < 256; k++) {
        int ks = (k + 128) & 255;                       // ifftshift index
        float coord = -128.0f + (float)ks * (256.0f / 255.0f);
        float g = expf(-(coord * coord) * inv2c2);
        int ph = (k * n) & 255;                          // exact phase mod N
        float th = (float)ph * (6.283185307179586f / 256.0f);
        re += g * cosf(th);
    }
    g_s1r[n] = re * (1.0f / 256.0f);

    if (n < 98) {
        int ic = n / 49, r = (n % 49) / 7, cc = n % 7;
        float v = sa7[ic * 49 + r * 7 + cc];
        if (r >= 1 && r <= 5 && cc >= 1 && cc <= 5) v += sa5[ic * 25 + (r - 1) * 5 + (cc - 1)];
        if (r >= 2 && r <= 4 && cc >= 2 && cc <= 4) v += sa3[ic * 9 + (r - 2) * 3 + (cc - 2)];
        g_sak[n] = v;
    }
    for (int i = n; i < Bn * Cn; i += 256) { g_lpsum[i] = 0.f; g_lpmax[i] = 0u; }
}

// ---------------- rel-pos bias table via tiny MLP ----------------------------
__global__ void k_bias(const float* __restrict__ w1, const float* __restrict__ b1,
                       const float* __restrict__ w2, const float* __restrict__ b2) {
    int g = blockIdx.x * 64 + threadIdx.x;   // 4096 pairs
    int n = g >> 6, m = g & 63;
    float d0 = (float)((n >> 3) - (m >> 3));
    float d1 = (float)((n & 7) - (m & 7));
    float s0 = (d0 > 0.f) - (d0 < 0.f), s1 = (d1 > 0.f) - (d1 < 0.f);
    float rp0 = s0 * log1pf(fabsf(d0));
    float rp1 = s1 * log1pf(fabsf(d1));
    float acc[NHn] = {};
    for (int r = 0; r < 256; r++) {
        float hv = fmaxf(fmaf(w1[r * 2], rp0, fmaf(w1[r * 2 + 1], rp1, b1[r])), 0.f);
        #pragma unroll
        for (int h = 0; h < NHn; h++) acc[h] = fmaf(w2[h * 256 + r], hv, acc[h]);
    }
    #pragma unroll
    for (int h = 0; h < NHn; h++) g_biasT[h * 4096 + g] = acc[h] + b2[h];
}

// ---------------- pack weights: paired bf16 [k2][o], Q pre-scaled -------------
__global__ void k_pack(const float* qw, const float* qb, const float* kw, const float* kb,
                       const float* vw, const float* vb, const float* pw) {
    int idx = blockIdx.x * 256 + threadIdx.x;   // 61440 threads
    if (idx < 96 * 640) {
        int k2 = idx / 640, o = idx % 640;
        int k = 2 * k2;
        float lo = 0.f, hi = 0.f;
        if (o < 192)       { lo = qw[o * 192 + k] * QSCALE; hi = qw[o * 192 + k + 1] * QSCALE; }
        else if (o < 384)  { lo = kw[(o - 192) * 192 + k]; hi = kw[(o - 192) * 192 + k + 1]; }
        else if (o < 576)  { lo = vw[(o - 384) * 192 + k]; hi = vw[(o - 384) * 192 + k + 1]; }
        g_apk[idx] = packbf(lo, hi);
    }
    if (idx < 96 * 256) {
        int k2 = idx / 256, o = idx % 256;
        int k = 2 * k2;
        float lo = (o < 192) ? pw[o * 192 + k] : 0.f;
        float hi = (o < 192) ? pw[o * 192 + k + 1] : 0.f;
        g_ppk[idx] = packbf(lo, hi);
    }
    if (idx < 3 * Cn) {
        float v = (idx < Cn) ? qb[idx] * QSCALE
                : ((idx < 2 * Cn) ? kb[idx - Cn] : vb[idx - 2 * Cn]);
        g_qkvb[idx] = v;
    }
}

// ---------------- fused separable freq filter: reg-batched sliding windows ----
__global__ __launch_bounds__(256, 4) void k_pass12(const float* __restrict__ x) {
    __shared__ float xs[84 * 52];
    __shared__ float rr[84 * 32];
    __shared__ float red[16];
    int tid = threadIdx.x;
    int bc = blockIdx.z;
    int h0 = blockIdx.y * 64, w0 = blockIdx.x * 32;
    size_t plane = (size_t)bc * HWn;

    // taps in registers (broadcast-cached in L1)
    float tp[NT];
    #pragma unroll
    for (int t = 0; t < NT; t++) tp[t] = g_s1r[(t - RAD + 256) & 255];

    // tile load with incremental row/col tracking (no divisions)
    {
        int r = tid / 52, c = tid - r * 52;     // one division total
        for (int i = tid; i < 84 * 52; i += 256) {
            int gh = (h0 + r - RAD) & 255, gw = (w0 + c - RAD) & 255;
            xs[i] = x[plane + gh * 256 + gw];
            c += 256 - 52 * 4;                   // advance by 256 = 4*52 + 48
            r += 4;
            if (c >= 52) { c -= 52; r += 1; }
        }
    }
    __syncthreads();

    // row pass: 84 rows x 4 eight-col segments; window via float4 LDS
    for (int task = tid; task < 84 * 4; task += 256) {
        int r = task >> 2, seg = task & 3;
        const float4* b4 = (const float4*)(xs + r * 52 + seg * 8);   // 4-aligned
        float win[28];
        #pragma unroll
        for (int q = 0; q < 7; q++) {
            float4 w4 = b4[q];
            win[q * 4 + 0] = w4.x; win[q * 4 + 1] = w4.y;
            win[q * 4 + 2] = w4.z; win[q * 4 + 3] = w4.w;
        }
        float acc[8];
        #pragma unroll
        for (int i = 0; i < 8; i++) acc[i] = 0.f;
        #pragma unroll
        for (int j = 0; j < 28; j++) {
            #pragma unroll
            for (int i = 0; i < 8; i++) {
                int t = i + 20 - j;
                if (t >= 0 && t < NT) acc[i] = fmaf(win[j], tp[t], acc[i]);
            }
        }
        float4* o4 = (float4*)(rr + r * 32 + seg * 8);               // 8-aligned
        o4[0] = make_float4(acc[0], acc[1], acc[2], acc[3]);
        o4[1] = make_float4(acc[4], acc[5], acc[6], acc[7]);
    }
    __syncthreads();

    // column pass: thread (ty,tx) -> rows ty*8..ty*8+7 at column tx
    int ty = tid >> 5, tx = tid & 31;
    float lsum = 0.f, lmax = 0.f;
    {
        float win[28];
        #pragma unroll
        for (int j = 0; j < 28; j++) win[j] = rr[(ty * 8 + j) * 32 + tx];
        float acc[8];
        #pragma unroll
        for (int i = 0; i < 8; i++) acc[i] = 0.f;
        #pragma unroll
        for (int j = 0; j < 28; j++) {
            #pragma unroll
            for (int i = 0; i < 8; i++) {
                int t = i + 20 - j;
                if (t >= 0 && t < NT) acc[i] = fmaf(win[j], tp[t], acc[i]);
            }
        }
        __half* hpout = g_hp + plane + (size_t)(h0 + ty * 8) * 256 + w0 + tx;
        #pragma unroll
        for (int i = 0; i < 8; i++) {
            float ar = acc[i];
            float xv = xs[(ty * 8 + i + 10) * 52 + tx + 10];
            float lp = fabsf(ar);
            hpout[i * 256] = __float2half(fabsf(xv - ar));
            lsum += lp;
            lmax = fmaxf(lmax, lp);
        }
    }
    // warp-shuffle reductions, one cross-warp stage
    #pragma unroll
    for (int st = 16; st > 0; st >>= 1) lsum += __shfl_xor_sync(0xffffffffu, lsum, st);
    if ((tid & 31) == 0) red[tid >> 5] = lsum;
    __syncthreads();
    if (tid == 0) {
        float s = 0.f;
        #pragma unroll
        for (int w = 0; w < 8; w++) s += red[w];
        atomicAdd(&g_lpsum[bc], s);
    }
    #pragma unroll
    for (int st = 16; st > 0; st >>= 1) lmax = fmaxf(lmax, __shfl_xor_sync(0xffffffffu, lmax, st));
    if ((tid & 31) == 0) red[8 + (tid >> 5)] = lmax;
    __syncthreads();
    if (tid == 0) {
        float m = red[8];
        #pragma unroll
        for (int w = 1; w < 8; w++) m = fmaxf(m, red[8 + w]);
        atomicMax(&g_lpmax[bc], __float_as_uint(m));
    }
}

// ---------------- hp channel mean/max per pixel (4 px/thread, fp16 src) -------
__global__ __launch_bounds__(256) void k_hpstats() {
    int g = blockIdx.x * 256 + threadIdx.x;   // 32768 pixel-quads
    int b = g >> 14, p = (g & 16383) * 4;
    float s[4] = {}, m[4] = {-1e30f, -1e30f, -1e30f, -1e30f};
    const __half* base = g_hp + (size_t)b * Cn * HWn + p;
    for (int c = 0; c < Cn; c++) {
        const __half2* h2 = (const __half2*)(base + (size_t)c * HWn);
        float2 v01 = __half22float2(h2[0]);
        float2 v23 = __half22float2(h2[1]);
        s[0] += v01.x; s[1] += v01.y; s[2] += v23.x; s[3] += v23.y;
        m[0] = fmaxf(m[0], v01.x); m[1] = fmaxf(m[1], v01.y);
        m[2] = fmaxf(m[2], v23.x); m[3] = fmaxf(m[3], v23.y);
    }
    int gp = b * HWn + p;
    #pragma unroll
    for (int i = 0; i < 4; i++) {
        g_smmean[gp + i] = s[i] * (1.0f / Cn);
        g_smmax[gp + i] = m[i];
    }
}

// ---------------- channel attention (tiny) -----------------------------------
__global__ void k_chanattn(const float* __restrict__ cw1, const float* __restrict__ cw2) {
    __shared__ float hs[Bn][12];
    int tid = threadIdx.x;
    if (tid < 24) {
        int b = tid / 12, j = tid % 12;
        float am = 0.f, ax = 0.f;
        for (int c = 0; c < Cn; c++) {
            float w = cw1[j * Cn + c];
            am = fmaf(w, g_lpsum[b * Cn + c] * (1.0f / HWn), am);
            ax = fmaf(w, __uint_as_float(g_lpmax[b * Cn + c]), ax);
        }
        hs[b][j] = fmaxf(am, 0.f) + fmaxf(ax, 0.f);
    }
    __syncthreads();
    for (int idx = tid; idx < Bn * Cn; idx += 256) {
        int b = idx / Cn, c = idx % Cn;
        float s = 0.f;
        #pragma unroll
        for (int j = 0; j < 12; j++) s = fmaf(cw2[c * 12 + j], hs[b][j], s);
        g_w1[idx] = 1.0f / (1.0f + __expf(-s));
    }
}

// ---------------- spatial attention 7x7 (zero pad, interior fast path) --------
__global__ __launch_bounds__(256) void k_spatattn() {
    int g = blockIdx.x * 256 + threadIdx.x;
    int b = g >> 16, p = g & 65535;
    int y = p >> 8, xx = p & 255;
    const float* s0 = g_smmean + (size_t)b * HWn;
    const float* s1p = g_smmax + (size_t)b * HWn;
    float acc = 0.f;
    if (y >= 3 && y <= 252 && xx >= 3 && xx <= 252) {
        #pragma unroll
        for (int dy = 0; dy < 7; dy++) {
            int row = (y + dy - 3) * 256 + xx - 3;
            #pragma unroll
            for (int dx = 0; dx < 7; dx++) {
                acc = fmaf(s0[row + dx], g_sak[dy * 7 + dx], acc);
                acc = fmaf(s1p[row + dx], g_sak[49 + dy * 7 + dx], acc);
            }
        }
    } else {
        for (int dy = 0; dy < 7; dy++) {
            int iy = y + dy - 3;
            if (iy < 0 || iy > 255) continue;
            for (int dx = 0; dx < 7; dx++) {
                int ix = xx + dx - 3;
                if (ix < 0 || ix > 255) continue;
                int o = iy * 256 + ix;
                acc = fmaf(s0[o], g_sak[dy * 7 + dx], acc);
                acc = fmaf(s1p[o], g_sak[49 + dy * 7 + dx], acc);
            }
        }
    }
    g_w2[g] = 1.0f / (1.0f + __expf(-acc));
}

// ---------------- fused scale + layernorm, 4 threads/pixel, single x read -----
__global__ __launch_bounds__(256) void k_ln(const float* __restrict__ x,
                                            const float* __restrict__ lnw,
                                            const float* __restrict__ lnb) {
    __shared__ float sred[2][4][64];
    int tid = threadIdx.x;
    int g = tid >> 6, pp = tid & 63;        // channel-group, pixel-in-block
    int b = blockIdx.y;
    int p = blockIdx.x * 64 + pp;
    float w2v = g_w2[b * HWn + p];
    int c0 = g * 48;
    const float* xb = x + (size_t)b * Cn * HWn + p;
    const float* w1b = g_w1 + b * Cn + c0;
    float v[48];
    float s = 0.f, s2 = 0.f;
    #pragma unroll
    for (int i = 0; i < 48; i++) {
        float vv = xb[(size_t)(c0 + i) * HWn] * w1b[i] * w2v;
        v[i] = vv;
        s += vv; s2 = fmaf(vv, vv, s2);
    }
    sred[0][g][pp] = s; sred[1][g][pp] = s2;
    __syncthreads();
    s  = sred[0][0][pp] + sred[0][1][pp] + sred[0][2][pp] + sred[0][3][pp];
    s2 = sred[1][0][pp] + sred[1][1][pp] + sred[1][2][pp] + sred[1][3][pp];
    float mu = s * (1.0f / Cn);
    float var = s2 * (1.0f / Cn) - mu * mu;
    float rstd = rsqrtf(var + 1e-5f);
    uint32_t* outb = g_xpk + (size_t)b * 96 * HWn + p;
    #pragma unroll
    for (int i = 0; i < 24; i++) {
        int c = c0 + 2 * i;
        float n0 = fmaf((v[2 * i]     - mu) * rstd, lnw[c],     lnb[c]);
        float n1 = fmaf((v[2 * i + 1] - mu) * rstd, lnw[c + 1], lnb[c + 1]);
        outb[(size_t)(g * 24 + i) * HWn] = packbf(n0, n1);
    }
}

// ---------------- bf16 tensor-core GEMM: full-B resident, loop over o-tiles ---
#define ASP 136
#define BSP 72
__global__ __launch_bounds__(256) void k_gemm_bf(int mode, const float* __restrict__ x_in,
                                                 const float* __restrict__ projb,
                                                 float* __restrict__ dout) {
    __shared__ uint32_t Bs[96 * BSP];       // full 192-channel B panel for 64 pixels
    __shared__ uint32_t As[2][16 * ASP];    // double-buffered A chunk
    int b = blockIdx.z;
    int numO = (mode == 0) ? 5 : 2;
    int ALD  = (mode == 0) ? 640 : 256;
    const uint32_t* A = (mode == 0) ? g_apk : g_ppk;
    int p0 = blockIdx.x * 64;
    int tid = threadIdx.x, lane = tid & 31, warp = tid >> 5;
    int gid = lane >> 2, tig = lane & 3;
    int wr = warp & 3, wc = warp >> 2;      // 4 (m) x 2 (n)

    // ---- load full B panel (96 k2-rows x 64 pixels) ----
    if (mode == 0) {
        #pragma unroll
        for (int l = 0; l < 6; l++) {
            int idx = l * 256 + tid;        // 1536 uint4
            int r = idx >> 4, c4 = idx & 15;
            *(uint4*)&Bs[r * BSP + c4 * 4] =
                *(const uint4*)&g_xpk[((size_t)(b * 96 + r)) * HWn + p0 + c4 * 4];
        }
    } else {
        #pragma unroll
        for (int l = 0; l < 6; l++) {
            int idx = l * 256 + tid;
            int r = idx >> 4, c4 = idx & 15;
            const float* src = g_sum + ((size_t)(b * 192 + r * 2)) * HWn + p0 + c4 * 4;
            float4 f0 = *(const float4*)src;
            float4 f1 = *(const float4*)(src + HWn);
            uint4 u;
            u.x = packbf(f0.x, f1.x); u.y = packbf(f0.y, f1.y);
            u.z = packbf(f0.z, f1.z); u.w = packbf(f0.w, f1.w);
            *(uint4*)&Bs[r * BSP + c4 * 4] = u;
        }
    }

    // ---- A prefetch coordinates ----
    int ar0 = tid >> 5, ac0 = (tid & 31) * 4;    // rows 0..7
    int ar1 = ar0 + 8;                           // rows 8..15

    // prefetch (ot=0, kt=0) and store to buffer 0
    {
        uint4 a0 = *(const uint4*)&A[(size_t)ar0 * ALD + ac0];
        uint4 a1 = *(const uint4*)&A[(size_t)ar1 * ALD + ac0];
        *(uint4*)&As[0][ar0 * ASP + ac0] = a0;
        *(uint4*)&As[0][ar1 * ASP + ac0] = a1;
    }
    __syncthreads();

    float d[2][4][4];
    int total = numO * 6;
    for (int it = 0; it < total; it++) {
        int ot = it / 6, kt = it - ot * 6;
        if (kt == 0) {
            #pragma unroll
            for (int i = 0; i < 2; i++)
                #pragma unroll
                for (int j = 0; j < 4; j++)
                    #pragma unroll
                    for (int r = 0; r < 4; r++) d[i][j][r] = 0.f;
        }
        // prefetch next chunk into regs (overlaps with mma)
        uint4 na0, na1;
        bool more = (it + 1 < total);
        if (more) {
            int nit = it + 1;
            int no0 = (nit / 6) * 128, nk = (nit % 6) * 16;
            na0 = *(const uint4*)&A[(size_t)(nk + ar0) * ALD + no0 + ac0];
            na1 = *(const uint4*)&A[(size_t)(nk + ar1) * ALD + no0 + ac0];
        }
        int buf = it & 1;
        #pragma unroll
        for (int s = 0; s < 2; s++) {
            uint32_t af[2][4], bfr[4][2];
            int kb = s * 8;
            #pragma unroll
            for (int mf = 0; mf < 2; mf++) {
                int ob = wr * 32 + mf * 16 + gid;
                af[mf][0] = As[buf][(kb + tig) * ASP + ob];
                af[mf][1] = As[buf][(kb + tig) * ASP + ob + 8];
                af[mf][2] = As[buf][(kb + tig + 4) * ASP + ob];
                af[mf][3] = As[buf][(kb + tig + 4) * ASP + ob + 8];
            }
            int krow = kt * 16 + kb;
            #pragma unroll
            for (int nf = 0; nf < 4; nf++) {
                int pb = wc * 32 + nf * 8 + gid;
                bfr[nf][0] = Bs[(krow + tig) * BSP + pb];
                bfr[nf][1] = Bs[(krow + tig + 4) * BSP + pb];
            }
            #pragma unroll
            for (int mf = 0; mf < 2; mf++)
                #pragma unroll
                for (int nf = 0; nf < 4; nf++)
                    mma_bf16(d[mf][nf], af[mf], bfr[nf]);
        }
        if (more) {
            *(uint4*)&As[buf ^ 1][ar0 * ASP + ac0] = na0;
            *(uint4*)&As[buf ^ 1][ar1 * ASP + ac0] = na1;
        }
        __syncthreads();

        if (kt == 5) {
            // ---- epilogue for o-tile ot ----
            int o0 = ot * 128;
            if (mode == 0) {
                #pragma unroll
                for (int mf = 0; mf < 2; mf++) {
                    #pragma unroll
                    for (int nf = 0; nf < 4; nf++) {
                        int p = p0 + wc * 32 + nf * 8 + tig * 2;
                        #pragma unroll
                        for (int half = 0; half < 2; half++) {
                            int o = o0 + wr * 32 + mf * 16 + gid + half * 8;
                            float v0 = d[mf][nf][half * 2 + 0];
                            float v1 = d[mf][nf][half * 2 + 1];
                            bool valid = (o < 576);
                            if (valid) {
                                float bia = g_qkvb[o];
                                v0 += bia; v1 += bia;
                                if (o < 192) {      // Q: add scaled prompt (fp16)
                                    __half2 hv = *(const __half2*)
                                        (g_hp + ((size_t)(b * 192 + o)) * HWn + p);
                                    float2 hf = __half22float2(hv);
                                    v0 = fmaf(hf.x, QSCALE, v0);
                                    v1 = fmaf(hf.y, QSCALE, v1);
                                }
                            }
                            float pv0 = __shfl_xor_sync(0xffffffffu, v0, 4);
                            float pv1 = __shfl_xor_sync(0xffffffffu, v1, 4);
                            if (valid) {
                                if (o >= 384) {     // V: fp16
                                    *(__half2*)(g_v + ((size_t)(b * 192 + o - 384)) * HWn + p)
                                        = __floats2half2_rn(v0, v1);
                                } else if ((gid & 1) == 0) {
                                    int o2 = (o < 192) ? (o >> 1) : (96 + ((o - 192) >> 1));
                                    uint2 u;
                                    u.x = packbf(v0, pv0);
                                    u.y = packbf(v1, pv1);
                                    *(uint2*)(g_qk + ((size_t)(b * 192 + o2)) * HWn + p) = u;
                                }
                            }
                        }
                    }
                }
            } else {
                #pragma unroll
                for (int mf = 0; mf < 2; mf++) {
                    int o_lo = o0 + wr * 32 + mf * 16 + gid;
                    #pragma unroll
                    for (int nf = 0; nf < 4; nf++) {
                        int p = p0 + wc * 32 + nf * 8 + tig * 2;
                        #pragma unroll
                        for (int half = 0; half < 2; half++) {
                            int o = o_lo + half * 8;
                            if (o >= 192) continue;
                            float v0 = d[mf][nf][half * 2 + 0];
                            float v1 = d[mf][nf][half * 2 + 1];
                            size_t xo = ((size_t)(b * Cn + o)) * HWn + p;
                            float wchan = g_w1[b * Cn + o];
                            float2 w2p = *(const float2*)(g_w2 + (size_t)b * HWn + p);
                            float2 xv = *(const float2*)(x_in + xo);
                            float pb = projb[o];
                            *(float2*)(dout + xo) = make_float2(v0 + pb + xv.x * wchan * w2p.x,
                                                                v1 + pb + xv.y * wchan * w2p.y);
                        }
                    }
                }
            }
        }
    }
}

// ---------------- depthwise 5x5 reflect conv on fp16 V -> g_sum ---------------
__global__ __launch_bounds__(256) void k_dw(const float* __restrict__ dww, const float* __restrict__ dwb) {
    __shared__ float tile[36 * 36];
    __shared__ float wv[25];
    int tid = threadIdx.x;
    int bc = blockIdx.z;
    int c = bc % Cn;
    int w0 = blockIdx.x * 32, h0 = blockIdx.y * 32;
    const __half* V = g_v + (size_t)bc * HWn;
    if (tid < 25) wv[tid] = dww[c * 25 + tid];
    for (int idx = tid; idx < 36 * 36; idx += 256) {
        int r = idx / 36, cc = idx - r * 36;
        int gy = h0 + r - 2;  if (gy < 0) gy = -gy;  if (gy > 255) gy = 510 - gy;
        int gx = w0 + cc - 2; if (gx < 0) gx = -gx;  if (gx > 255) gx = 510 - gx;
        tile[idx] = __half2float(V[gy * 256 + gx]);
    }
    __syncthreads();
    int tx = tid & 31, ty0 = (tid >> 5) * 4;
    float bias = dwb[c];
    #pragma unroll
    for (int i = 0; i < 4; i++) {
        int ry = ty0 + i;
        float acc = 0.f;
        #pragma unroll
        for (int dy = 0; dy < 5; dy++)
            #pragma unroll
            for (int dx = 0; dx < 5; dx++)
                acc = fmaf(tile[(ry + dy) * 36 + tx + dx], wv[dy * 5 + dx], acc);
        g_sum[(size_t)bc * HWn + (h0 + ry) * 256 + w0 + tx] = acc + bias;
    }
}

// ---------------- tensor-core window attention --------------------------------
#define QP 20
#define VP 36
__global__ __launch_bounds__(64) void k_attn() {
    __shared__ uint32_t qpk[64 * QP];
    __shared__ uint32_t kpk[64 * QP];
    __shared__ uint32_t vpk[32 * VP];
    int bid = blockIdx.x;
    int h = bid % NHn; int win = bid / NHn;
    int wx = win & 31, wy = (win >> 5) & 31, b = win >> 10;
    int tid = threadIdx.x, lane = tid & 31, w = tid >> 5;
    int gid = lane >> 2, tig = lane & 3;
    int ch0 = h * HDn, q2 = h * 16;
    size_t pbase = (size_t)(wy * 8) * 256 + wx * 8;

    // stage Q,K: direct channel-paired uint32 loads
    {
        int t = tid;
        size_t po = pbase + (t >> 3) * 256 + (t & 7);
        const uint32_t* qb = g_qk + (size_t)(b * 192) * HWn + po;
        #pragma unroll
        for (int i = 0; i < 16; i++) {
            qpk[t * QP + i] = qb[(size_t)(q2 + i) * HWn];
            kpk[t * QP + i] = qb[(size_t)(96 + q2 + i) * HWn];
        }
    }
    // stage V: token-paired from fp16 (adjacent tokens = one half2)
    for (int idx = tid; idx < 32 * 32; idx += 64) {
        int dd = idx >> 5, t2 = idx & 31;
        int t = t2 * 2;
        size_t po = pbase + (t >> 3) * 256 + (t & 7);
        float2 vv = __half22float2(*(const __half2*)
            (g_v + ((size_t)(b * 192 + ch0 + dd)) * HWn + po));
        vpk[dd * VP + t2] = packbf(vv.x, vv.y);
    }
    __syncthreads();

    // S = Q K^T  (each warp: rows 32w..32w+31)
    float sf[2][8][4];
    #pragma unroll
    for (int mt = 0; mt < 2; mt++)
        #pragma unroll
        for (int nt = 0; nt < 8; nt++)
            #pragma unroll
            for (int r = 0; r < 4; r++) sf[mt][nt][r] = 0.f;
    int mrow = w * 32;
    #pragma unroll
    for (int s = 0; s < 2; s++) {
        uint32_t af[2][4];
        #pragma unroll
        for (int mt = 0; mt < 2; mt++) {
            int rb = (mrow + mt * 16 + gid) * QP + s * 8;
            af[mt][0] = qpk[rb + tig];
            af[mt][1] = qpk[rb + 8 * QP + tig];
            af[mt][2] = qpk[rb + tig + 4];
            af[mt][3] = qpk[rb + 8 * QP + tig + 4];
        }
        #pragma unroll
        for (int nt = 0; nt < 8; nt++) {
            uint32_t bfr[2];
            int rb = (nt * 8 + gid) * QP + s * 8;
            bfr[0] = kpk[rb + tig];
            bfr[1] = kpk[rb + tig + 4];
            #pragma unroll
            for (int mt = 0; mt < 2; mt++)
                mma_bf16(sf[mt][nt], af[mt], bfr);
        }
    }

    // bias + softmax (rows live in 4-lane quads)
    float den[2][2];
    #pragma unroll
    for (int mt = 0; mt < 2; mt++) {
        #pragma unroll
        for (int rh = 0; rh < 2; rh++) {
            int irow = mrow + mt * 16 + rh * 8 + gid;
            const float* br = g_biasT + h * 4096 + irow * 64 + tig * 2;
            float mx = -1e30f;
            #pragma unroll
            for (int nt = 0; nt < 8; nt++) {
                float2 bb = *(const float2*)(br + nt * 8);
                float s0 = sf[mt][nt][rh * 2 + 0] + bb.x;
                float s1 = sf[mt][nt][rh * 2 + 1] + bb.y;
                sf[mt][nt][rh * 2 + 0] = s0;
                sf[mt][nt][rh * 2 + 1] = s1;
                mx = fmaxf(mx, fmaxf(s0, s1));
            }
            mx = fmaxf(mx, __shfl_xor_sync(0xffffffffu, mx, 1));
            mx = fmaxf(mx, __shfl_xor_sync(0xffffffffu, mx, 2));
            float ds = 0.f;
            #pragma unroll
            for (int nt = 0; nt < 8; nt++) {
                float e0 = __expf(sf[mt][nt][rh * 2 + 0] - mx);
                float e1 = __expf(sf[mt][nt][rh * 2 + 1] - mx);
                sf[mt][nt][rh * 2 + 0] = e0;
                sf[mt][nt][rh * 2 + 1] = e1;
                ds += e0 + e1;
            }
            ds += __shfl_xor_sync(0xffffffffu, ds, 1);
            ds += __shfl_xor_sync(0xffffffffu, ds, 2);
            den[mt][rh] = ds;
        }
    }

    // repack P as A-fragments
    uint32_t apv[2][4][4];
    #pragma unroll
    for (int mt = 0; mt < 2; mt++)
        #pragma unroll
        for (int kt = 0; kt < 4; kt++) {
            apv[mt][kt][0] = packbf(sf[mt][2 * kt][0],     sf[mt][2 * kt][1]);
            apv[mt][kt][1] = packbf(sf[mt][2 * kt][2],     sf[mt][2 * kt][3]);
            apv[mt][kt][2] = packbf(sf[mt][2 * kt + 1][0], sf[mt][2 * kt + 1][1]);
            apv[mt][kt][3] = packbf(sf[mt][2 * kt + 1][2], sf[mt][2 * kt + 1][3]);
        }

    // O = P V
    float of[2][4][4];
    #pragma unroll
    for (int mt = 0; mt < 2; mt++)
        #pragma unroll
        for (int vn = 0; vn < 4; vn++)
            #pragma unroll
            for (int r = 0; r < 4; r++) of[mt][vn][r] = 0.f;
    #pragma unroll
    for (int kt = 0; kt < 4; kt++) {
        uint32_t bfr[4][2];
        #pragma unroll
        for (int vn = 0; vn < 4; vn++) {
            int rb = (vn * 8 + gid) * VP + kt * 8;
            bfr[vn][0] = vpk[rb + tig];
            bfr[vn][1] = vpk[rb + tig + 4];
        }
        #pragma unroll
        for (int mt = 0; mt < 2; mt++)
            #pragma unroll
            for (int vn = 0; vn < 4; vn++)
                mma_bf16(of[mt][vn], apv[mt][kt], bfr[vn]);
    }

    // write: g_sum += O / den
    #pragma unroll
    for (int mt = 0; mt < 2; mt++)
        #pragma unroll
        for (int rh = 0; rh < 2; rh++) {
            int irow = mrow + mt * 16 + rh * 8 + gid;
            size_t po = pbase + (irow >> 3) * 256 + (irow & 7);
            float inv = 1.0f / den[mt][rh];
            #pragma unroll
            for (int vn = 0; vn < 4; vn++) {
                int dd = vn * 8 + tig * 2;
                float* gp = g_sum + ((size_t)(b * 192 + ch0 + dd)) * HWn + po;
                gp[0]   += of[mt][vn][rh * 2 + 0] * inv;
                gp[HWn] += of[mt][vn][rh * 2 + 1] * inv;
            }
        }
}

// ------------------------------ launch ---------------------------------------
extern "C" void kernel_launch(void* const* d_in, const int* in_sizes, int n_in,
                              void* d_out, int out_size) {
    const float* x      = (const float*)d_in[0];
    const float* ln_w   = (const float*)d_in[1];
    const float* ln_b   = (const float*)d_in[2];
    const float* ca_w1  = (const float*)d_in[3];
    const float* ca_w2  = (const float*)d_in[4];
    const float* sa_w3  = (const float*)d_in[5];
    const float* sa_w5  = (const float*)d_in[6];
    const float* sa_w7  = (const float*)d_in[7];
    const float* q_w    = (const float*)d_in[8];
    const float* q_b    = (const float*)d_in[9];
    const float* k_w    = (const float*)d_in[10];
    const float* k_b    = (const float*)d_in[11];
    const float* v_w    = (const float*)d_in[12];
    const float* v_b    = (const float*)d_in[13];
    const float* proj_w = (const float*)d_in[14];
    const float* proj_b = (const float*)d_in[15];
    const float* m_w1   = (const float*)d_in[16];
    const float* m_b1   = (const float*)d_in[17];
    const float* m_w2   = (const float*)d_in[18];
    const float* m_b2   = (const float*)d_in[19];
    const float* dw_w   = (const float*)d_in[20];
    const float* dw_b   = (const float*)d_in[21];
    float* out = (float*)d_out;

    k_setup<<<1, 256>>>(sa_w3, sa_w5, sa_w7);
    k_bias<<<64, 64>>>(m_w1, m_b1, m_w2, m_b2);
    k_pack<<<240, 256>>>(q_w, q_b, k_w, k_b, v_w, v_b, proj_w);

    k_pass12<<<dim3(8, 4, Bn * Cn), 256>>>(x);
    k_hpstats<<<128, 256>>>();
    k_chanattn<<<1, 256>>>(ca_w1, ca_w2);
    k_spatattn<<<(Bn * HWn) / 256, 256>>>();
    k_ln<<<dim3(HWn / 64, Bn), 256>>>(x, ln_w, ln_b);

    k_gemm_bf<<<dim3(HWn / 64, 1, Bn), 256>>>(0, nullptr, nullptr, nullptr);
    k_dw<<<dim3(Wn / 32, Hn / 32, Bn * Cn), 256>>>(dw_w, dw_b);
    k_attn<<<Bn * 32 * 32 * NHn, 64>>>();
    k_gemm_bf<<<dim3(HWn / 64, 1, Bn), 256>>>(1, x, proj_b, out);
}

// round 16
// speedup vs baseline: 1.0635x; 1.0635x over previous
#include <cuda_runtime.h>
#include <cuda_bf16.h>
#include <cuda_fp16.h>
#include <math.h>
#include <stdint.h>

// Problem constants
#define Bn 2
#define Cn 192
#define Hn 256
#define Wn 256
#define HWn 65536
#define NHn 6
#define HDn 32
#define RAD 10
#define NT  21            // 2*RAD+1 taps
#define BCHW (2*192*65536)
#define QSCALE 0.17677669529663689f

// ---------------- scratch (device globals; no runtime allocation) -------------
__device__ __half   g_hp[BCHW];           // highpass magnitude (= prompt), fp16
__device__ uint32_t g_qk[2*192*65536];    // Q pairs (0..95) K pairs (96..191), per batch
__device__ __half   g_v[BCHW];            // V fp16 [b][c][p]
__device__ float    g_sum[BCHW];          // dwconv + attention output (fp32)
__device__ float    g_smmean[Bn*HWn];
__device__ float    g_smmax [Bn*HWn];
__device__ float    g_w2    [Bn*HWn];
__device__ float    g_lpsum[Bn*Cn];
__device__ unsigned g_lpmax[Bn*Cn];
__device__ float    g_w1[Bn*Cn];
__device__ float    g_s1r[256];           // 1D spatial kernel (real part)
__device__ float    g_sak[2*49];          // combined 7x7 spatial-attn kernel
__device__ float    g_biasT[NHn*64*64];   // rel-pos bias table
__device__ uint32_t g_apk[96*640];        // qkv weights paired-bf16 [k2][o] (Q pre-scaled)
__device__ uint32_t g_ppk[96*256];        // proj weights paired-bf16 [k2][o]
__device__ float    g_qkvb[3*Cn];         // (Q bias pre-scaled)

__device__ __forceinline__ uint32_t packbf(float lo, float hi) {
    __nv_bfloat162 h = __floats2bfloat162_rn(lo, hi);
    return *(uint32_t*)&h;
}

__device__ __forceinline__ void mma_bf16(float* d, const uint32_t* a, const uint32_t* b) {
    asm volatile("mma.sync.aligned.m16n8k16.row.col.f32.bf16.bf16.f32 "
        "{%0,%1,%2,%3}, {%4,%5,%6,%7}, {%8,%9}, {%0,%1,%2,%3};"
        : "+f"(d[0]), "+f"(d[1]), "+f"(d[2]), "+f"(d[3])
        : "r"(a[0]), "r"(a[1]), "r"(a[2]), "r"(a[3]), "r"(b[0]), "r"(b[1]));
}

// ---------------- setup: s1 kernel + combined SA kernel + zero stats ----------
__global__ void k_setup(const float* __restrict__ sa3, const float* __restrict__ sa5,
                        const float* __restrict__ sa7) {
    int n = threadIdx.x;  // 256 threads
    float re = 0.f;
    const float inv2c2 = 1.0f / (2.0f * 25.6f * 25.6f);
    for (int k = 0; k < 256; k++) {
        int ks = (k + 128) & 255;                       // ifftshift index
        float coord = -128.0f + (float)ks * (256.0f / 255.0f);
        float g = expf(-(coord * coord) * inv2c2);
        int ph = (k * n) & 255;                          // exact phase mod N
        float th = (float)ph * (6.283185307179586f / 256.0f);
        re += g * cosf(th);
    }
    g_s1r[n] = re * (1.0f / 256.0f);

    if (n < 98) {
        int ic = n / 49, r = (n % 49) / 7, cc = n % 7;
        float v = sa7[ic * 49 + r * 7 + cc];
        if (r >= 1 && r <= 5 && cc >= 1 && cc <= 5) v += sa5[ic * 25 + (r - 1) * 5 + (cc - 1)];
        if (r >= 2 && r <= 4 && cc >= 2 && cc <= 4) v += sa3[ic * 9 + (r - 2) * 3 + (cc - 2)];
        g_sak[n] = v;
    }
    for (int i = n; i < Bn * Cn; i += 256) { g_lpsum[i] = 0.f; g_lpmax[i] = 0u; }
}

// ---------------- rel-pos bias table via tiny MLP ----------------------------
__global__ void k_bias(const float* __restrict__ w1, const float* __restrict__ b1,
                       const float* __restrict__ w2, const float* __restrict__ b2) {
    int g = blockIdx.x * 64 + threadIdx.x;   // 4096 pairs
    int n = g >> 6, m = g & 63;
    float d0 = (float)((n >> 3) - (m >> 3));
    float d1 = (float)((n & 7) - (m & 7));
    float s0 = (d0 > 0.f) - (d0 < 0.f), s1 = (d1 > 0.f) - (d1 < 0.f);
    float rp0 = s0 * log1pf(fabsf(d0));
    float rp1 = s1 * log1pf(fabsf(d1));
    float acc[NHn] = {};
    for (int r = 0; r < 256; r++) {
        float hv = fmaxf(fmaf(w1[r * 2], rp0, fmaf(w1[r * 2 + 1], rp1, b1[r])), 0.f);
        #pragma unroll
        for (int h = 0; h < NHn; h++) acc[h] = fmaf(w2[h * 256 + r], hv, acc[h]);
    }
    #pragma unroll
    for (int h = 0; h < NHn; h++) g_biasT[h * 4096 + g] = acc[h] + b2[h];
}

// ---------------- pack weights: paired bf16 [k2][o], Q pre-scaled -------------
__global__ void k_pack(const float* qw, const float* qb, const float* kw, const float* kb,
                       const float* vw, const float* vb, const float* pw) {
    int idx = blockIdx.x * 256 + threadIdx.x;   // 61440 threads
    if (idx < 96 * 640) {
        int k2 = idx / 640, o = idx % 640;
        int k = 2 * k2;
        float lo = 0.f, hi = 0.f;
        if (o < 192)       { lo = qw[o * 192 + k] * QSCALE; hi = qw[o * 192 + k + 1] * QSCALE; }
        else if (o < 384)  { lo = kw[(o - 192) * 192 + k]; hi = kw[(o - 192) * 192 + k + 1]; }
        else if (o < 576)  { lo = vw[(o - 384) * 192 + k]; hi = vw[(o - 384) * 192 + k + 1]; }
        g_apk[idx] = packbf(lo, hi);
    }
    if (idx < 96 * 256) {
        int k2 = idx / 256, o = idx % 256;
        int k = 2 * k2;
        float lo = (o < 192) ? pw[o * 192 + k] : 0.f;
        float hi = (o < 192) ? pw[o * 192 + k + 1] : 0.f;
        g_ppk[idx] = packbf(lo, hi);
    }
    if (idx < 3 * Cn) {
        float v = (idx < Cn) ? qb[idx] * QSCALE
                : ((idx < 2 * Cn) ? kb[idx - Cn] : vb[idx - 2 * Cn]);
        g_qkvb[idx] = v;
    }
}

// ---------------- fused separable freq filter: reg-batched sliding windows ----
__global__ __launch_bounds__(256) void k_pass12(const float* __restrict__ x) {
    __shared__ float xs[84 * 52];
    __shared__ float rr[84 * 32];
    __shared__ float red[16];
    int tid = threadIdx.x;
    int bc = blockIdx.z;
    int h0 = blockIdx.y * 64, w0 = blockIdx.x * 32;
    size_t plane = (size_t)bc * HWn;

    // taps in registers (broadcast-cached in L1)
    float tp[NT];
    #pragma unroll
    for (int t = 0; t < NT; t++) tp[t] = g_s1r[(t - RAD + 256) & 255];

    // tile load with incremental row/col tracking (no divisions)
    {
        int r = tid / 52, c = tid - r * 52;     // one division total
        for (int i = tid; i < 84 * 52; i += 256) {
            int gh = (h0 + r - RAD) & 255, gw = (w0 + c - RAD) & 255;
            xs[i] = x[plane + gh * 256 + gw];
            c += 256 - 52 * 4;                   // advance by 256 = 4*52 + 48
            r += 4;
            if (c >= 52) { c -= 52; r += 1; }
        }
    }
    __syncthreads();

    // row pass: 84 rows x 4 eight-col segments; window via float4 LDS
    for (int task = tid; task < 84 * 4; task += 256) {
        int r = task >> 2, seg = task & 3;
        const float4* b4 = (const float4*)(xs + r * 52 + seg * 8);   // 4-aligned
        float win[28];
        #pragma unroll
        for (int q = 0; q < 7; q++) {
            float4 w4 = b4[q];
            win[q * 4 + 0] = w4.x; win[q * 4 + 1] = w4.y;
            win[q * 4 + 2] = w4.z; win[q * 4 + 3] = w4.w;
        }
        float acc[8];
        #pragma unroll
        for (int i = 0; i < 8; i++) acc[i] = 0.f;
        #pragma unroll
        for (int j = 0; j < 28; j++) {
            #pragma unroll
            for (int i = 0; i < 8; i++) {
                int t = i + 20 - j;
                if (t >= 0 && t < NT) acc[i] = fmaf(win[j], tp[t], acc[i]);
            }
        }
        float4* o4 = (float4*)(rr + r * 32 + seg * 8);               // 8-aligned
        o4[0] = make_float4(acc[0], acc[1], acc[2], acc[3]);
        o4[1] = make_float4(acc[4], acc[5], acc[6], acc[7]);
    }
    __syncthreads();

    // column pass: thread (ty,tx) -> rows ty*8..ty*8+7 at column tx
    int ty = tid >> 5, tx = tid & 31;
    float lsum = 0.f, lmax = 0.f;
    {
        float win[28];
        #pragma unroll
        for (int j = 0; j < 28; j++) win[j] = rr[(ty * 8 + j) * 32 + tx];
        float acc[8];
        #pragma unroll
        for (int i = 0; i < 8; i++) acc[i] = 0.f;
        #pragma unroll
        for (int j = 0; j < 28; j++) {
            #pragma unroll
            for (int i = 0; i < 8; i++) {
                int t = i + 20 - j;
                if (t >= 0 && t < NT) acc[i] = fmaf(win[j], tp[t], acc[i]);
            }
        }
        __half* hpout = g_hp + plane + (size_t)(h0 + ty * 8) * 256 + w0 + tx;
        #pragma unroll
        for (int i = 0; i < 8; i++) {
            float ar = acc[i];
            float xv = xs[(ty * 8 + i + 10) * 52 + tx + 10];
            float lp = fabsf(ar);
            hpout[i * 256] = __float2half(fabsf(xv - ar));
            lsum += lp;
            lmax = fmaxf(lmax, lp);
        }
    }
    // warp-shuffle reductions, one cross-warp stage
    #pragma unroll
    for (int st = 16; st > 0; st >>= 1) lsum += __shfl_xor_sync(0xffffffffu, lsum, st);
    if ((tid & 31) == 0) red[tid >> 5] = lsum;
    __syncthreads();
    if (tid == 0) {
        float s = 0.f;
        #pragma unroll
        for (int w = 0; w < 8; w++) s += red[w];
        atomicAdd(&g_lpsum[bc], s);
    }
    #pragma unroll
    for (int st = 16; st > 0; st >>= 1) lmax = fmaxf(lmax, __shfl_xor_sync(0xffffffffu, lmax, st));
    if ((tid & 31) == 0) red[8 + (tid >> 5)] = lmax;
    __syncthreads();
    if (tid == 0) {
        float m = red[8];
        #pragma unroll
        for (int w = 1; w < 8; w++) m = fmaxf(m, red[8 + w]);
        atomicMax(&g_lpmax[bc], __float_as_uint(m));
    }
}

// ---------------- hp channel mean/max per pixel (4 px/thread, fp16 src) -------
__global__ __launch_bounds__(256) void k_hpstats() {
    int g = blockIdx.x * 256 + threadIdx.x;   // 32768 pixel-quads
    int b = g >> 14, p = (g & 16383) * 4;
    float s[4] = {}, m[4] = {-1e30f, -1e30f, -1e30f, -1e30f};
    const __half* base = g_hp + (size_t)b * Cn * HWn + p;
    for (int c = 0; c < Cn; c++) {
        const __half2* h2 = (const __half2*)(base + (size_t)c * HWn);
        float2 v01 = __half22float2(h2[0]);
        float2 v23 = __half22float2(h2[1]);
        s[0] += v01.x; s[1] += v01.y; s[2] += v23.x; s[3] += v23.y;
        m[0] = fmaxf(m[0], v01.x); m[1] = fmaxf(m[1], v01.y);
        m[2] = fmaxf(m[2], v23.x); m[3] = fmaxf(m[3], v23.y);
    }
    int gp = b * HWn + p;
    #pragma unroll
    for (int i = 0; i < 4; i++) {
        g_smmean[gp + i] = s[i] * (1.0f / Cn);
        g_smmax[gp + i] = m[i];
    }
}

// ---------------- channel attention (tiny) -----------------------------------
__global__ void k_chanattn(const float* __restrict__ cw1, const float* __restrict__ cw2) {
    __shared__ float hs[Bn][12];
    int tid = threadIdx.x;
    if (tid < 24) {
        int b = tid / 12, j = tid % 12;
        float am = 0.f, ax = 0.f;
        for (int c = 0; c < Cn; c++) {
            float w = cw1[j * Cn + c];
            am = fmaf(w, g_lpsum[b * Cn + c] * (1.0f / HWn), am);
            ax = fmaf(w, __uint_as_float(g_lpmax[b * Cn + c]), ax);
        }
        hs[b][j] = fmaxf(am, 0.f) + fmaxf(ax, 0.f);
    }
    __syncthreads();
    for (int idx = tid; idx < Bn * Cn; idx += 256) {
        int b = idx / Cn, c = idx % Cn;
        float s = 0.f;
        #pragma unroll
        for (int j = 0; j < 12; j++) s = fmaf(cw2[c * 12 + j], hs[b][j], s);
        g_w1[idx] = 1.0f / (1.0f + __expf(-s));
    }
}

// ---------------- spatial attention 7x7 (zero pad, interior fast path) --------
__global__ __launch_bounds__(256) void k_spatattn() {
    int g = blockIdx.x * 256 + threadIdx.x;
    int b = g >> 16, p = g & 65535;
    int y = p >> 8, xx = p & 255;
    const float* s0 = g_smmean + (size_t)b * HWn;
    const float* s1p = g_smmax + (size_t)b * HWn;
    float acc = 0.f;
    if (y >= 3 && y <= 252 && xx >= 3 && xx <= 252) {
        #pragma unroll
        for (int dy = 0; dy < 7; dy++) {
            int row = (y + dy - 3) * 256 + xx - 3;
            #pragma unroll
            for (int dx = 0; dx < 7; dx++) {
                acc = fmaf(s0[row + dx], g_sak[dy * 7 + dx], acc);
                acc = fmaf(s1p[row + dx], g_sak[49 + dy * 7 + dx], acc);
            }
        }
    } else {
        for (int dy = 0; dy < 7; dy++) {
            int iy = y + dy - 3;
            if (iy < 0 || iy > 255) continue;
            for (int dx = 0; dx < 7; dx++) {
                int ix = xx + dx - 3;
                if (ix < 0 || ix > 255) continue;
                int o = iy * 256 + ix;
                acc = fmaf(s0[o], g_sak[dy * 7 + dx], acc);
                acc = fmaf(s1p[o], g_sak[49 + dy * 7 + dx], acc);
            }
        }
    }
    g_w2[g] = 1.0f / (1.0f + __expf(-acc));
}

// ---------------- bf16 tensor-core GEMM: full-B resident, LN fused (mode 0) ---
#define ASP 136
#define BSP 72
__global__ __launch_bounds__(256) void k_gemm_bf(int mode, const float* __restrict__ x_in,
                                                 const float* __restrict__ projb,
                                                 float* __restrict__ dout,
                                                 const float* __restrict__ lnw,
                                                 const float* __restrict__ lnb) {
    __shared__ uint32_t Bs[96 * BSP];       // full 192-channel B panel for 64 pixels
    __shared__ uint32_t As[2][16 * ASP];    // double-buffered A chunk
    __shared__ float sred[2][4][64];
    int b = blockIdx.z;
    int numO = (mode == 0) ? 5 : 2;
    int ALD  = (mode == 0) ? 640 : 256;
    const uint32_t* A = (mode == 0) ? g_apk : g_ppk;
    int p0 = blockIdx.x * 64;
    int tid = threadIdx.x, lane = tid & 31, warp = tid >> 5;
    int gid = lane >> 2, tig = lane & 3;
    int wr = warp & 3, wc = warp >> 2;      // 4 (m) x 2 (n)

    // ---- build full B panel (96 k2-rows x 64 pixels) ----
    if (mode == 0) {
        // fused scale + layernorm directly from x (4 threads per pixel)
        int g = tid >> 6, pp = tid & 63;
        float w2v = g_w2[b * HWn + p0 + pp];
        int c0 = g * 48;
        const float* xb = x_in + (size_t)b * Cn * HWn + p0 + pp;
        const float* w1b = g_w1 + b * Cn + c0;
        float v[48];
        float s = 0.f, s2 = 0.f;
        #pragma unroll
        for (int i = 0; i < 48; i++) {
            float vv = xb[(size_t)(c0 + i) * HWn] * w1b[i] * w2v;
            v[i] = vv;
            s += vv; s2 = fmaf(vv, vv, s2);
        }
        sred[0][g][pp] = s; sred[1][g][pp] = s2;
        __syncthreads();
        s  = sred[0][0][pp] + sred[0][1][pp] + sred[0][2][pp] + sred[0][3][pp];
        s2 = sred[1][0][pp] + sred[1][1][pp] + sred[1][2][pp] + sred[1][3][pp];
        float mu = s * (1.0f / Cn);
        float var = s2 * (1.0f / Cn) - mu * mu;
        float rstd = rsqrtf(var + 1e-5f);
        #pragma unroll
        for (int i = 0; i < 24; i++) {
            int c = c0 + 2 * i;
            float n0 = fmaf((v[2 * i]     - mu) * rstd, lnw[c],     lnb[c]);
            float n1 = fmaf((v[2 * i + 1] - mu) * rstd, lnw[c + 1], lnb[c + 1]);
            Bs[(g * 24 + i) * BSP + pp] = packbf(n0, n1);
        }
    } else {
        #pragma unroll
        for (int l = 0; l < 6; l++) {
            int idx = l * 256 + tid;
            int r = idx >> 4, c4 = idx & 15;
            const float* src = g_sum + ((size_t)(b * 192 + r * 2)) * HWn + p0 + c4 * 4;
            float4 f0 = *(const float4*)src;
            float4 f1 = *(const float4*)(src + HWn);
            uint4 u;
            u.x = packbf(f0.x, f1.x); u.y = packbf(f0.y, f1.y);
            u.z = packbf(f0.z, f1.z); u.w = packbf(f0.w, f1.w);
            *(uint4*)&Bs[r * BSP + c4 * 4] = u;
        }
    }

    // ---- A prefetch coordinates ----
    int ar0 = tid >> 5, ac0 = (tid & 31) * 4;    // rows 0..7
    int ar1 = ar0 + 8;                           // rows 8..15

    // prefetch (ot=0, kt=0) and store to buffer 0
    {
        uint4 a0 = *(const uint4*)&A[(size_t)ar0 * ALD + ac0];
        uint4 a1 = *(const uint4*)&A[(size_t)ar1 * ALD + ac0];
        *(uint4*)&As[0][ar0 * ASP + ac0] = a0;
        *(uint4*)&As[0][ar1 * ASP + ac0] = a1;
    }
    __syncthreads();

    float d[2][4][4];
    int total = numO * 6;
    for (int it = 0; it < total; it++) {
        int ot = it / 6, kt = it - ot * 6;
        if (kt == 0) {
            #pragma unroll
            for (int i = 0; i < 2; i++)
                #pragma unroll
                for (int j = 0; j < 4; j++)
                    #pragma unroll
                    for (int r = 0; r < 4; r++) d[i][j][r] = 0.f;
        }
        // prefetch next chunk into regs (overlaps with mma)
        uint4 na0, na1;
        bool more = (it + 1 < total);
        if (more) {
            int nit = it + 1;
            int no0 = (nit / 6) * 128, nk = (nit % 6) * 16;
            na0 = *(const uint4*)&A[(size_t)(nk + ar0) * ALD + no0 + ac0];
            na1 = *(const uint4*)&A[(size_t)(nk + ar1) * ALD + no0 + ac0];
        }
        int buf = it & 1;
        #pragma unroll
        for (int s = 0; s < 2; s++) {
            uint32_t af[2][4], bfr[4][2];
            int kb = s * 8;
            #pragma unroll
            for (int mf = 0; mf < 2; mf++) {
                int ob = wr * 32 + mf * 16 + gid;
                af[mf][0] = As[buf][(kb + tig) * ASP + ob];
                af[mf][1] = As[buf][(kb + tig) * ASP + ob + 8];
                af[mf][2] = As[buf][(kb + tig + 4) * ASP + ob];
                af[mf][3] = As[buf][(kb + tig + 4) * ASP + ob + 8];
            }
            int krow = kt * 16 + kb;
            #pragma unroll
            for (int nf = 0; nf < 4; nf++) {
                int pb = wc * 32 + nf * 8 + gid;
                bfr[nf][0] = Bs[(krow + tig) * BSP + pb];
                bfr[nf][1] = Bs[(krow + tig + 4) * BSP + pb];
            }
            #pragma unroll
            for (int mf = 0; mf < 2; mf++)
                #pragma unroll
                for (int nf = 0; nf < 4; nf++)
                    mma_bf16(d[mf][nf], af[mf], bfr[nf]);
        }
        if (more) {
            *(uint4*)&As[buf ^ 1][ar0 * ASP + ac0] = na0;
            *(uint4*)&As[buf ^ 1][ar1 * ASP + ac0] = na1;
        }
        __syncthreads();

        if (kt == 5) {
            // ---- epilogue for o-tile ot ----
            int o0 = ot * 128;
            if (mode == 0) {
                #pragma unroll
                for (int mf = 0; mf < 2; mf++) {
                    #pragma unroll
                    for (int nf = 0; nf < 4; nf++) {
                        int p = p0 + wc * 32 + nf * 8 + tig * 2;
                        #pragma unroll
                        for (int half = 0; half < 2; half++) {
                            int o = o0 + wr * 32 + mf * 16 + gid + half * 8;
                            float v0 = d[mf][nf][half * 2 + 0];
                            float v1 = d[mf][nf][half * 2 + 1];
                            bool valid = (o < 576);
                            if (valid) {
                                float bia = g_qkvb[o];
                                v0 += bia; v1 += bia;
                                if (o < 192) {      // Q: add scaled prompt (fp16)
                                    __half2 hv = *(const __half2*)
                                        (g_hp + ((size_t)(b * 192 + o)) * HWn + p);
                                    float2 hf = __half22float2(hv);
                                    v0 = fmaf(hf.x, QSCALE, v0);
                                    v1 = fmaf(hf.y, QSCALE, v1);
                                }
                            }
                            float pv0 = __shfl_xor_sync(0xffffffffu, v0, 4);
                            float pv1 = __shfl_xor_sync(0xffffffffu, v1, 4);
                            if (valid) {
                                if (o >= 384) {     // V: fp16
                                    *(__half2*)(g_v + ((size_t)(b * 192 + o - 384)) * HWn + p)
                                        = __floats2half2_rn(v0, v1);
                                } else if ((gid & 1) == 0) {
                                    int o2 = (o < 192) ? (o >> 1) : (96 + ((o - 192) >> 1));
                                    uint2 u;
                                    u.x = packbf(v0, pv0);
                                    u.y = packbf(v1, pv1);
                                    *(uint2*)(g_qk + ((size_t)(b * 192 + o2)) * HWn + p) = u;
                                }
                            }
                        }
                    }
                }
            } else {
                #pragma unroll
                for (int mf = 0; mf < 2; mf++) {
                    int o_lo = o0 + wr * 32 + mf * 16 + gid;
                    #pragma unroll
                    for (int nf = 0; nf < 4; nf++) {
                        int p = p0 + wc * 32 + nf * 8 + tig * 2;
                        #pragma unroll
                        for (int half = 0; half < 2; half++) {
                            int o = o_lo + half * 8;
                            if (o >= 192) continue;
                            float v0 = d[mf][nf][half * 2 + 0];
                            float v1 = d[mf][nf][half * 2 + 1];
                            size_t xo = ((size_t)(b * Cn + o)) * HWn + p;
                            float wchan = g_w1[b * Cn + o];
                            float2 w2p = *(const float2*)(g_w2 + (size_t)b * HWn + p);
                            float2 xv = *(const float2*)(x_in + xo);
                            float pb = projb[o];
                            *(float2*)(dout + xo) = make_float2(v0 + pb + xv.x * wchan * w2p.x,
                                                                v1 + pb + xv.y * wchan * w2p.y);
                        }
                    }
                }
            }
        }
    }
}

// ---------------- depthwise 5x5 reflect conv on fp16 V -> g_sum ---------------
__global__ __launch_bounds__(256) void k_dw(const float* __restrict__ dww, const float* __restrict__ dwb) {
    __shared__ float tile[36 * 36];
    __shared__ float wv[25];
    int tid = threadIdx.x;
    int bc = blockIdx.z;
    int c = bc % Cn;
    int w0 = blockIdx.x * 32, h0 = blockIdx.y * 32;
    const __half* V = g_v + (size_t)bc * HWn;
    if (tid < 25) wv[tid] = dww[c * 25 + tid];
    for (int idx = tid; idx < 36 * 36; idx += 256) {
        int r = idx / 36, cc = idx - r * 36;
        int gy = h0 + r - 2;  if (gy < 0) gy = -gy;  if (gy > 255) gy = 510 - gy;
        int gx = w0 + cc - 2; if (gx < 0) gx = -gx;  if (gx > 255) gx = 510 - gx;
        tile[idx] = __half2float(V[gy * 256 + gx]);
    }
    __syncthreads();
    int tx = tid & 31, ty0 = (tid >> 5) * 4;
    float bias = dwb[c];
    #pragma unroll
    for (int i = 0; i < 4; i++) {
        int ry = ty0 + i;
        float acc = 0.f;
        #pragma unroll
        for (int dy = 0; dy < 5; dy++)
            #pragma unroll
            for (int dx = 0; dx < 5; dx++)
                acc = fmaf(tile[(ry + dy) * 36 + tx + dx], wv[dy * 5 + dx], acc);
        g_sum[(size_t)bc * HWn + (h0 + ry) * 256 + w0 + tx] = acc + bias;
    }
}

// ---------------- tensor-core window attention --------------------------------
#define QP 20
#define VP 36
__global__ __launch_bounds__(64) void k_attn() {
    __shared__ uint32_t qpk[64 * QP];
    __shared__ uint32_t kpk[64 * QP];
    __shared__ uint32_t vpk[32 * VP];
    int bid = blockIdx.x;
    int h = bid % NHn; int win = bid / NHn;
    int wx = win & 31, wy = (win >> 5) & 31, b = win >> 10;
    int tid = threadIdx.x, lane = tid & 31, w = tid >> 5;
    int gid = lane >> 2, tig = lane & 3;
    int ch0 = h * HDn, q2 = h * 16;
    size_t pbase = (size_t)(wy * 8) * 256 + wx * 8;

    // stage Q,K: direct channel-paired uint32 loads
    {
        int t = tid;
        size_t po = pbase + (t >> 3) * 256 + (t & 7);
        const uint32_t* qb = g_qk + (size_t)(b * 192) * HWn + po;
        #pragma unroll
        for (int i = 0; i < 16; i++) {
            qpk[t * QP + i] = qb[(size_t)(q2 + i) * HWn];
            kpk[t * QP + i] = qb[(size_t)(96 + q2 + i) * HWn];
        }
    }
    // stage V: token-paired from fp16 (adjacent tokens = one half2)
    for (int idx = tid; idx < 32 * 32; idx += 64) {
        int dd = idx >> 5, t2 = idx & 31;
        int t = t2 * 2;
        size_t po = pbase + (t >> 3) * 256 + (t & 7);
        float2 vv = __half22float2(*(const __half2*)
            (g_v + ((size_t)(b * 192 + ch0 + dd)) * HWn + po));
        vpk[dd * VP + t2] = packbf(vv.x, vv.y);
    }
    __syncthreads();

    // S = Q K^T  (each warp: rows 32w..32w+31)
    float sf[2][8][4];
    #pragma unroll
    for (int mt = 0; mt < 2; mt++)
        #pragma unroll
        for (int nt = 0; nt < 8; nt++)
            #pragma unroll
            for (int r = 0; r < 4; r++) sf[mt][nt][r] = 0.f;
    int mrow = w * 32;
    #pragma unroll
    for (int s = 0; s < 2; s++) {
        uint32_t af[2][4];
        #pragma unroll
        for (int mt = 0; mt < 2; mt++) {
            int rb = (mrow + mt * 16 + gid) * QP + s * 8;
            af[mt][0] = qpk[rb + tig];
            af[mt][1] = qpk[rb + 8 * QP + tig];
            af[mt][2] = qpk[rb + tig + 4];
            af[mt][3] = qpk[rb + 8 * QP + tig + 4];
        }
        #pragma unroll
        for (int nt = 0; nt < 8; nt++) {
            uint32_t bfr[2];
            int rb = (nt * 8 + gid) * QP + s * 8;
            bfr[0] = kpk[rb + tig];
            bfr[1] = kpk[rb + tig + 4];
            #pragma unroll
            for (int mt = 0; mt < 2; mt++)
                mma_bf16(sf[mt][nt], af[mt], bfr);
        }
    }

    // bias + softmax (rows live in 4-lane quads)
    float den[2][2];
    #pragma unroll
    for (int mt = 0; mt < 2; mt++) {
        #pragma unroll
        for (int rh = 0; rh < 2; rh++) {
            int irow = mrow + mt * 16 + rh * 8 + gid;
            const float* br = g_biasT + h * 4096 + irow * 64 + tig * 2;
            float mx = -1e30f;
            #pragma unroll
            for (int nt = 0; nt < 8; nt++) {
                float2 bb = *(const float2*)(br + nt * 8);
                float s0 = sf[mt][nt][rh * 2 + 0] + bb.x;
                float s1 = sf[mt][nt][rh * 2 + 1] + bb.y;
                sf[mt][nt][rh * 2 + 0] = s0;
                sf[mt][nt][rh * 2 + 1] = s1;
                mx = fmaxf(mx, fmaxf(s0, s1));
            }
            mx = fmaxf(mx, __shfl_xor_sync(0xffffffffu, mx, 1));
            mx = fmaxf(mx, __shfl_xor_sync(0xffffffffu, mx, 2));
            float ds = 0.f;
            #pragma unroll
            for (int nt = 0; nt < 8; nt++) {
                float e0 = __expf(sf[mt][nt][rh * 2 + 0] - mx);
                float e1 = __expf(sf[mt][nt][rh * 2 + 1] - mx);
                sf[mt][nt][rh * 2 + 0] = e0;
                sf[mt][nt][rh * 2 + 1] = e1;
                ds += e0 + e1;
            }
            ds += __shfl_xor_sync(0xffffffffu, ds, 1);
            ds += __shfl_xor_sync(0xffffffffu, ds, 2);
            den[mt][rh] = ds;
        }
    }

    // repack P as A-fragments
    uint32_t apv[2][4][4];
    #pragma unroll
    for (int mt = 0; mt < 2; mt++)
        #pragma unroll
        for (int kt = 0; kt < 4; kt++) {
            apv[mt][kt][0] = packbf(sf[mt][2 * kt][0],     sf[mt][2 * kt][1]);
            apv[mt][kt][1] = packbf(sf[mt][2 * kt][2],     sf[mt][2 * kt][3]);
            apv[mt][kt][2] = packbf(sf[mt][2 * kt + 1][0], sf[mt][2 * kt + 1][1]);
            apv[mt][kt][3] = packbf(sf[mt][2 * kt + 1][2], sf[mt][2 * kt + 1][3]);
        }

    // O = P V
    float of[2][4][4];
    #pragma unroll
    for (int mt = 0; mt < 2; mt++)
        #pragma unroll
        for (int vn = 0; vn < 4; vn++)
            #pragma unroll
            for (int r = 0; r < 4; r++) of[mt][vn][r] = 0.f;
    #pragma unroll
    for (int kt = 0; kt < 4; kt++) {
        uint32_t bfr[4][2];
        #pragma unroll
        for (int vn = 0; vn < 4; vn++) {
            int rb = (vn * 8 + gid) * VP + kt * 8;
            bfr[vn][0] = vpk[rb + tig];
            bfr[vn][1] = vpk[rb + tig + 4];
        }
        #pragma unroll
        for (int mt = 0; mt < 2; mt++)
            #pragma unroll
            for (int vn = 0; vn < 4; vn++)
                mma_bf16(of[mt][vn], apv[mt][kt], bfr[vn]);
    }

    // write: g_sum += O / den
    #pragma unroll
    for (int mt = 0; mt < 2; mt++)
        #pragma unroll
        for (int rh = 0; rh < 2; rh++) {
            int irow = mrow + mt * 16 + rh * 8 + gid;
            size_t po = pbase + (irow >> 3) * 256 + (irow & 7);
            float inv = 1.0f / den[mt][rh];
            #pragma unroll
            for (int vn = 0; vn < 4; vn++) {
                int dd = vn * 8 + tig * 2;
                float* gp = g_sum + ((size_t)(b * 192 + ch0 + dd)) * HWn + po;
                gp[0]   += of[mt][vn][rh * 2 + 0] * inv;
                gp[HWn] += of[mt][vn][rh * 2 + 1] * inv;
            }
        }
}

// ------------------------------ launch ---------------------------------------
extern "C" void kernel_launch(void* const* d_in, const int* in_sizes, int n_in,
                              void* d_out, int out_size) {
    const float* x      = (const float*)d_in[0];
    const float* ln_w   = (const float*)d_in[1];
    const float* ln_b   = (const float*)d_in[2];
    const float* ca_w1  = (const float*)d_in[3];
    const float* ca_w2  = (const float*)d_in[4];
    const float* sa_w3  = (const float*)d_in[5];
    const float* sa_w5  = (const float*)d_in[6];
    const float* sa_w7  = (const float*)d_in[7];
    const float* q_w    = (const float*)d_in[8];
    const float* q_b    = (const float*)d_in[9];
    const float* k_w    = (const float*)d_in[10];
    const float* k_b    = (const float*)d_in[11];
    const float* v_w    = (const float*)d_in[12];
    const float* v_b    = (const float*)d_in[13];
    const float* proj_w = (const float*)d_in[14];
    const float* proj_b = (const float*)d_in[15];
    const float* m_w1   = (const float*)d_in[16];
    const float* m_b1   = (const float*)d_in[17];
    const float* m_w2   = (const float*)d_in[18];
    const float* m_b2   = (const float*)d_in[19];
    const float* dw_w   = (const float*)d_in[20];
    const float* dw_b   = (const float*)d_in[21];
    float* out = (float*)d_out;

    k_setup<<<1, 256>>>(sa_w3, sa_w5, sa_w7);
    k_bias<<<64, 64>>>(m_w1, m_b1, m_w2, m_b2);
    k_pack<<<240, 256>>>(q_w, q_b, k_w, k_b, v_w, v_b, proj_w);

    k_pass12<<<dim3(8, 4, Bn * Cn), 256>>>(x);
    k_hpstats<<<128, 256>>>();
    k_chanattn<<<1, 256>>>(ca_w1, ca_w2);
    k_spatattn<<<(Bn * HWn) / 256, 256>>>();

    k_gemm_bf<<<dim3(HWn / 64, 1, Bn), 256>>>(0, x, nullptr, nullptr, ln_w, ln_b);
    k_dw<<<dim3(Wn / 32, Hn / 32, Bn * Cn), 256>>>(dw_w, dw_b);
    k_attn<<<Bn * 32 * 32 * NHn, 64>>>();
    k_gemm_bf<<<dim3(HWn / 64, 1, Bn), 256>>>(1, x, proj_b, out, nullptr, nullptr);
}

// round 17
// speedup vs baseline: 1.1380x; 1.0700x over previous
#include <cuda_runtime.h>
#include <cuda_bf16.h>
#include <cuda_fp16.h>
#include <math.h>
#include <stdint.h>

// Problem constants
#define Bn 2
#define Cn 192
#define Hn 256
#define Wn 256
#define HWn 65536
#define NHn 6
#define HDn 32
#define RAD 10
#define NT  21            // 2*RAD+1 taps
#define BCHW (2*192*65536)
#define QSCALE 0.17677669529663689f

// ---------------- scratch (device globals; no runtime allocation) -------------
__device__ __half   g_hp[BCHW];           // highpass magnitude (= prompt), fp16
__device__ uint32_t g_qk[2*192*65536];    // Q pairs (0..95) K pairs (96..191), per batch
__device__ __half   g_v[BCHW];            // V fp16 [b][c][p]
__device__ float    g_sum[BCHW];          // dwconv output (fp32)
__device__ float    g_attn[BCHW];         // attention output (fp32, pure stores)
__device__ float    g_smmean[Bn*HWn];
__device__ float    g_smmax [Bn*HWn];
__device__ float    g_w2    [Bn*HWn];
__device__ float    g_lpsum[Bn*Cn];
__device__ unsigned g_lpmax[Bn*Cn];
__device__ float    g_w1[Bn*Cn];
__device__ float    g_s1r[256];           // 1D spatial kernel (real part)
__device__ float    g_sak[2*49];          // combined 7x7 spatial-attn kernel
__device__ float    g_biasT[NHn*64*64];   // rel-pos bias table
__device__ uint32_t g_apk[96*640];        // qkv weights paired-bf16 [k2][o] (Q pre-scaled)
__device__ uint32_t g_ppk[96*256];        // proj weights paired-bf16 [k2][o]
__device__ float    g_qkvb[3*Cn];         // (Q bias pre-scaled)

__device__ __forceinline__ uint32_t packbf(float lo, float hi) {
    __nv_bfloat162 h = __floats2bfloat162_rn(lo, hi);
    return *(uint32_t*)&h;
}

__device__ __forceinline__ void mma_bf16(float* d, const uint32_t* a, const uint32_t* b) {
    asm volatile("mma.sync.aligned.m16n8k16.row.col.f32.bf16.bf16.f32 "
        "{%0,%1,%2,%3}, {%4,%5,%6,%7}, {%8,%9}, {%0,%1,%2,%3};"
        : "+f"(d[0]), "+f"(d[1]), "+f"(d[2]), "+f"(d[3])
        : "r"(a[0]), "r"(a[1]), "r"(a[2]), "r"(a[3]), "r"(b[0]), "r"(b[1]));
}

// ---------------- setup: s1 kernel + combined SA kernel + zero stats ----------
__global__ void k_setup(const float* __restrict__ sa3, const float* __restrict__ sa5,
                        const float* __restrict__ sa7) {
    int n = threadIdx.x;  // 256 threads
    float re = 0.f;
    const float inv2c2 = 1.0f / (2.0f * 25.6f * 25.6f);
    for (int k = 0; k < 256; k++) {
        int ks = (k + 128) & 255;                       // ifftshift index
        float coord = -128.0f + (float)ks * (256.0f / 255.0f);
        float g = expf(-(coord * coord) * inv2c2);
        int ph = (k * n) & 255;                          // exact phase mod N
        float th = (float)ph * (6.283185307179586f / 256.0f);
        re += g * cosf(th);
    }
    g_s1r[n] = re * (1.0f / 256.0f);

    if (n < 98) {
        int ic = n / 49, r = (n % 49) / 7, cc = n % 7;
        float v = sa7[ic * 49 + r * 7 + cc];
        if (r >= 1 && r <= 5 && cc >= 1 && cc <= 5) v += sa5[ic * 25 + (r - 1) * 5 + (cc - 1)];
        if (r >= 2 && r <= 4 && cc >= 2 && cc <= 4) v += sa3[ic * 9 + (r - 2) * 3 + (cc - 2)];
        g_sak[n] = v;
    }
    for (int i = n; i < Bn * Cn; i += 256) { g_lpsum[i] = 0.f; g_lpmax[i] = 0u; }
}

// ---------------- rel-pos bias table via tiny MLP ----------------------------
__global__ void k_bias(const float* __restrict__ w1, const float* __restrict__ b1,
                       const float* __restrict__ w2, const float* __restrict__ b2) {
    int g = blockIdx.x * 64 + threadIdx.x;   // 4096 pairs
    int n = g >> 6, m = g & 63;
    float d0 = (float)((n >> 3) - (m >> 3));
    float d1 = (float)((n & 7) - (m & 7));
    float s0 = (d0 > 0.f) - (d0 < 0.f), s1 = (d1 > 0.f) - (d1 < 0.f);
    float rp0 = s0 * log1pf(fabsf(d0));
    float rp1 = s1 * log1pf(fabsf(d1));
    float acc[NHn] = {};
    for (int r = 0; r < 256; r++) {
        float hv = fmaxf(fmaf(w1[r * 2], rp0, fmaf(w1[r * 2 + 1], rp1, b1[r])), 0.f);
        #pragma unroll
        for (int h = 0; h < NHn; h++) acc[h] = fmaf(w2[h * 256 + r], hv, acc[h]);
    }
    #pragma unroll
    for (int h = 0; h < NHn; h++) g_biasT[h * 4096 + g] = acc[h] + b2[h];
}

// ---------------- pack weights: paired bf16 [k2][o], Q pre-scaled -------------
__global__ void k_pack(const float* qw, const float* qb, const float* kw, const float* kb,
                       const float* vw, const float* vb, const float* pw) {
    int idx = blockIdx.x * 256 + threadIdx.x;   // 61440 threads
    if (idx < 96 * 640) {
        int k2 = idx / 640, o = idx % 640;
        int k = 2 * k2;
        float lo = 0.f, hi = 0.f;
        if (o < 192)       { lo = qw[o * 192 + k] * QSCALE; hi = qw[o * 192 + k + 1] * QSCALE; }
        else if (o < 384)  { lo = kw[(o - 192) * 192 + k]; hi = kw[(o - 192) * 192 + k + 1]; }
        else if (o < 576)  { lo = vw[(o - 384) * 192 + k]; hi = vw[(o - 384) * 192 + k + 1]; }
        g_apk[idx] = packbf(lo, hi);
    }
    if (idx < 96 * 256) {
        int k2 = idx / 256, o = idx % 256;
        int k = 2 * k2;
        float lo = (o < 192) ? pw[o * 192 + k] : 0.f;
        float hi = (o < 192) ? pw[o * 192 + k + 1] : 0.f;
        g_ppk[idx] = packbf(lo, hi);
    }
    if (idx < 3 * Cn) {
        float v = (idx < Cn) ? qb[idx] * QSCALE
                : ((idx < 2 * Cn) ? kb[idx - Cn] : vb[idx - 2 * Cn]);
        g_qkvb[idx] = v;
    }
}

// ---------------- fused separable freq filter: reg-batched sliding windows ----
__global__ __launch_bounds__(256) void k_pass12(const float* __restrict__ x) {
    __shared__ float xs[84 * 52];
    __shared__ float rr[84 * 32];
    __shared__ float red[16];
    int tid = threadIdx.x;
    int bc = blockIdx.z;
    int h0 = blockIdx.y * 64, w0 = blockIdx.x * 32;
    size_t plane = (size_t)bc * HWn;

    // taps in registers (broadcast-cached in L1)
    float tp[NT];
    #pragma unroll
    for (int t = 0; t < NT; t++) tp[t] = g_s1r[(t - RAD + 256) & 255];

    // tile load with incremental row/col tracking (no divisions)
    {
        int r = tid / 52, c = tid - r * 52;     // one division total
        for (int i = tid; i < 84 * 52; i += 256) {
            int gh = (h0 + r - RAD) & 255, gw = (w0 + c - RAD) & 255;
            xs[i] = x[plane + gh * 256 + gw];
            c += 256 - 52 * 4;                   // advance by 256 = 4*52 + 48
            r += 4;
            if (c >= 52) { c -= 52; r += 1; }
        }
    }
    __syncthreads();

    // row pass: 84 rows x 4 eight-col segments; window via float4 LDS
    for (int task = tid; task < 84 * 4; task += 256) {
        int r = task >> 2, seg = task & 3;
        const float4* b4 = (const float4*)(xs + r * 52 + seg * 8);   // 4-aligned
        float win[28];
        #pragma unroll
        for (int q = 0; q < 7; q++) {
            float4 w4 = b4[q];
            win[q * 4 + 0] = w4.x; win[q * 4 + 1] = w4.y;
            win[q * 4 + 2] = w4.z; win[q * 4 + 3] = w4.w;
        }
        float acc[8];
        #pragma unroll
        for (int i = 0; i < 8; i++) acc[i] = 0.f;
        #pragma unroll
        for (int j = 0; j < 28; j++) {
            #pragma unroll
            for (int i = 0; i < 8; i++) {
                int t = i + 20 - j;
                if (t >= 0 && t < NT) acc[i] = fmaf(win[j], tp[t], acc[i]);
            }
        }
        float4* o4 = (float4*)(rr + r * 32 + seg * 8);               // 8-aligned
        o4[0] = make_float4(acc[0], acc[1], acc[2], acc[3]);
        o4[1] = make_float4(acc[4], acc[5], acc[6], acc[7]);
    }
    __syncthreads();

    // column pass: thread (ty,tx) -> rows ty*8..ty*8+7 at column tx
    int ty = tid >> 5, tx = tid & 31;
    float lsum = 0.f, lmax = 0.f;
    {
        float win[28];
        #pragma unroll
        for (int j = 0; j < 28; j++) win[j] = rr[(ty * 8 + j) * 32 + tx];
        float acc[8];
        #pragma unroll
        for (int i = 0; i < 8; i++) acc[i] = 0.f;
        #pragma unroll
        for (int j = 0; j < 28; j++) {
            #pragma unroll
            for (int i = 0; i < 8; i++) {
                int t = i + 20 - j;
                if (t >= 0 && t < NT) acc[i] = fmaf(win[j], tp[t], acc[i]);
            }
        }
        __half* hpout = g_hp + plane + (size_t)(h0 + ty * 8) * 256 + w0 + tx;
        #pragma unroll
        for (int i = 0; i < 8; i++) {
            float ar = acc[i];
            float xv = xs[(ty * 8 + i + 10) * 52 + tx + 10];
            float lp = fabsf(ar);
            hpout[i * 256] = __float2half(fabsf(xv - ar));
            lsum += lp;
            lmax = fmaxf(lmax, lp);
        }
    }
    // warp-shuffle reductions, one cross-warp stage
    #pragma unroll
    for (int st = 16; st > 0; st >>= 1) lsum += __shfl_xor_sync(0xffffffffu, lsum, st);
    if ((tid & 31) == 0) red[tid >> 5] = lsum;
    __syncthreads();
    if (tid == 0) {
        float s = 0.f;
        #pragma unroll
        for (int w = 0; w < 8; w++) s += red[w];
        atomicAdd(&g_lpsum[bc], s);
    }
    #pragma unroll
    for (int st = 16; st > 0; st >>= 1) lmax = fmaxf(lmax, __shfl_xor_sync(0xffffffffu, lmax, st));
    if ((tid & 31) == 0) red[8 + (tid >> 5)] = lmax;
    __syncthreads();
    if (tid == 0) {
        float m = red[8];
        #pragma unroll
        for (int w = 1; w < 8; w++) m = fmaxf(m, red[8 + w]);
        atomicMax(&g_lpmax[bc], __float_as_uint(m));
    }
}

// ---------------- hp channel mean/max per pixel (4 px/thread, fp16 src) -------
__global__ __launch_bounds__(256) void k_hpstats() {
    int g = blockIdx.x * 256 + threadIdx.x;   // 32768 pixel-quads
    int b = g >> 14, p = (g & 16383) * 4;
    float s[4] = {}, m[4] = {-1e30f, -1e30f, -1e30f, -1e30f};
    const __half* base = g_hp + (size_t)b * Cn * HWn + p;
    for (int c = 0; c < Cn; c++) {
        const __half2* h2 = (const __half2*)(base + (size_t)c * HWn);
        float2 v01 = __half22float2(h2[0]);
        float2 v23 = __half22float2(h2[1]);
        s[0] += v01.x; s[1] += v01.y; s[2] += v23.x; s[3] += v23.y;
        m[0] = fmaxf(m[0], v01.x); m[1] = fmaxf(m[1], v01.y);
        m[2] = fmaxf(m[2], v23.x); m[3] = fmaxf(m[3], v23.y);
    }
    int gp = b * HWn + p;
    #pragma unroll
    for (int i = 0; i < 4; i++) {
        g_smmean[gp + i] = s[i] * (1.0f / Cn);
        g_smmax[gp + i] = m[i];
    }
}

// ---------------- channel attention (tiny) -----------------------------------
__global__ void k_chanattn(const float* __restrict__ cw1, const float* __restrict__ cw2) {
    __shared__ float hs[Bn][12];
    int tid = threadIdx.x;
    if (tid < 24) {
        int b = tid / 12, j = tid % 12;
        float am = 0.f, ax = 0.f;
        for (int c = 0; c < Cn; c++) {
            float w = cw1[j * Cn + c];
            am = fmaf(w, g_lpsum[b * Cn + c] * (1.0f / HWn), am);
            ax = fmaf(w, __uint_as_float(g_lpmax[b * Cn + c]), ax);
        }
        hs[b][j] = fmaxf(am, 0.f) + fmaxf(ax, 0.f);
    }
    __syncthreads();
    for (int idx = tid; idx < Bn * Cn; idx += 256) {
        int b = idx / Cn, c = idx % Cn;
        float s = 0.f;
        #pragma unroll
        for (int j = 0; j < 12; j++) s = fmaf(cw2[c * 12 + j], hs[b][j], s);
        g_w1[idx] = 1.0f / (1.0f + __expf(-s));
    }
}

// ---------------- spatial attention 7x7 (zero pad, interior fast path) --------
__global__ __launch_bounds__(256) void k_spatattn() {
    int g = blockIdx.x * 256 + threadIdx.x;
    int b = g >> 16, p = g & 65535;
    int y = p >> 8, xx = p & 255;
    const float* s0 = g_smmean + (size_t)b * HWn;
    const float* s1p = g_smmax + (size_t)b * HWn;
    float acc = 0.f;
    if (y >= 3 && y <= 252 && xx >= 3 && xx <= 252) {
        #pragma unroll
        for (int dy = 0; dy < 7; dy++) {
            int row = (y + dy - 3) * 256 + xx - 3;
            #pragma unroll
            for (int dx = 0; dx < 7; dx++) {
                acc = fmaf(s0[row + dx], g_sak[dy * 7 + dx], acc);
                acc = fmaf(s1p[row + dx], g_sak[49 + dy * 7 + dx], acc);
            }
        }
    } else {
        for (int dy = 0; dy < 7; dy++) {
            int iy = y + dy - 3;
            if (iy < 0 || iy > 255) continue;
            for (int dx = 0; dx < 7; dx++) {
                int ix = xx + dx - 3;
                if (ix < 0 || ix > 255) continue;
                int o = iy * 256 + ix;
                acc = fmaf(s0[o], g_sak[dy * 7 + dx], acc);
                acc = fmaf(s1p[o], g_sak[49 + dy * 7 + dx], acc);
            }
        }
    }
    g_w2[g] = 1.0f / (1.0f + __expf(-acc));
}

// ---------------- bf16 tensor-core GEMM: full-B resident, LN fused (mode 0) ---
#define ASP 136
#define BSP 72
__global__ __launch_bounds__(256) void k_gemm_bf(int mode, const float* __restrict__ x_in,
                                                 const float* __restrict__ projb,
                                                 float* __restrict__ dout,
                                                 const float* __restrict__ lnw,
                                                 const float* __restrict__ lnb) {
    __shared__ uint32_t Bs[96 * BSP];       // full 192-channel B panel for 64 pixels
    __shared__ uint32_t As[2][16 * ASP];    // double-buffered A chunk
    __shared__ float sred[2][4][64];
    int b = blockIdx.z;
    int numO = (mode == 0) ? 5 : 2;
    int OC   = (mode == 0) ? 576 : 192;
    int ALD  = (mode == 0) ? 640 : 256;
    const uint32_t* A = (mode == 0) ? g_apk : g_ppk;
    int p0 = blockIdx.x * 64;
    int tid = threadIdx.x, lane = tid & 31, warp = tid >> 5;
    int gid = lane >> 2, tig = lane & 3;
    int wr = warp & 3, wc = warp >> 2;      // 4 (m) x 2 (n)

    // ---- build full B panel (96 k2-rows x 64 pixels) ----
    if (mode == 0) {
        // fused scale + layernorm directly from x (4 threads per pixel)
        int g = tid >> 6, pp = tid & 63;
        float w2v = g_w2[b * HWn + p0 + pp];
        int c0 = g * 48;
        const float* xb = x_in + (size_t)b * Cn * HWn + p0 + pp;
        const float* w1b = g_w1 + b * Cn + c0;
        float v[48];
        float s = 0.f, s2 = 0.f;
        #pragma unroll
        for (int i = 0; i < 48; i++) {
            float vv = xb[(size_t)(c0 + i) * HWn] * w1b[i] * w2v;
            v[i] = vv;
            s += vv; s2 = fmaf(vv, vv, s2);
        }
        sred[0][g][pp] = s; sred[1][g][pp] = s2;
        __syncthreads();
        s  = sred[0][0][pp] + sred[0][1][pp] + sred[0][2][pp] + sred[0][3][pp];
        s2 = sred[1][0][pp] + sred[1][1][pp] + sred[1][2][pp] + sred[1][3][pp];
        float mu = s * (1.0f / Cn);
        float var = s2 * (1.0f / Cn) - mu * mu;
        float rstd = rsqrtf(var + 1e-5f);
        #pragma unroll
        for (int i = 0; i < 24; i++) {
            int c = c0 + 2 * i;
            float n0 = fmaf((v[2 * i]     - mu) * rstd, lnw[c],     lnb[c]);
            float n1 = fmaf((v[2 * i + 1] - mu) * rstd, lnw[c + 1], lnb[c + 1]);
            Bs[(g * 24 + i) * BSP + pp] = packbf(n0, n1);
        }
    } else {
        #pragma unroll
        for (int l = 0; l < 6; l++) {
            int idx = l * 256 + tid;
            int r = idx >> 4, c4 = idx & 15;
            size_t off = ((size_t)(b * 192 + r * 2)) * HWn + p0 + c4 * 4;
            float4 f0 = *(const float4*)(g_sum + off);
            float4 f1 = *(const float4*)(g_sum + off + HWn);
            float4 a0 = *(const float4*)(g_attn + off);
            float4 a1 = *(const float4*)(g_attn + off + HWn);
            f0.x += a0.x; f0.y += a0.y; f0.z += a0.z; f0.w += a0.w;
            f1.x += a1.x; f1.y += a1.y; f1.z += a1.z; f1.w += a1.w;
            uint4 u;
            u.x = packbf(f0.x, f1.x); u.y = packbf(f0.y, f1.y);
            u.z = packbf(f0.z, f1.z); u.w = packbf(f0.w, f1.w);
            *(uint4*)&Bs[r * BSP + c4 * 4] = u;
        }
    }

    // ---- A prefetch coordinates ----
    int ar0 = tid >> 5, ac0 = (tid & 31) * 4;    // rows 0..7
    int ar1 = ar0 + 8;                           // rows 8..15

    // prefetch (ot=0, kt=0) and store to buffer 0
    {
        uint4 a0 = *(const uint4*)&A[(size_t)ar0 * ALD + ac0];
        uint4 a1 = *(const uint4*)&A[(size_t)ar1 * ALD + ac0];
        *(uint4*)&As[0][ar0 * ASP + ac0] = a0;
        *(uint4*)&As[0][ar1 * ASP + ac0] = a1;
    }
    __syncthreads();

    float d[2][4][4];
    int total = numO * 6;
    for (int it = 0; it < total; it++) {
        int ot = it / 6, kt = it - ot * 6;
        if (kt == 0) {
            #pragma unroll
            for (int i = 0; i < 2; i++)
                #pragma unroll
                for (int j = 0; j < 4; j++)
                    #pragma unroll
                    for (int r = 0; r < 4; r++) d[i][j][r] = 0.f;
        }
        // prefetch next chunk into regs (overlaps with mma)
        uint4 na0, na1;
        bool more = (it + 1 < total);
        if (more) {
            int nit = it + 1;
            int no0 = (nit / 6) * 128, nk = (nit % 6) * 16;
            na0 = *(const uint4*)&A[(size_t)(nk + ar0) * ALD + no0 + ac0];
            na1 = *(const uint4*)&A[(size_t)(nk + ar1) * ALD + no0 + ac0];
        }
        int buf = it & 1;
        if (ot * 128 + wr * 32 < OC) {      // skip padding-only m-rows
            #pragma unroll
            for (int s = 0; s < 2; s++) {
                uint32_t af[2][4], bfr[4][2];
                int kb = s * 8;
                #pragma unroll
                for (int mf = 0; mf < 2; mf++) {
                    int ob = wr * 32 + mf * 16 + gid;
                    af[mf][0] = As[buf][(kb + tig) * ASP + ob];
                    af[mf][1] = As[buf][(kb + tig) * ASP + ob + 8];
                    af[mf][2] = As[buf][(kb + tig + 4) * ASP + ob];
                    af[mf][3] = As[buf][(kb + tig + 4) * ASP + ob + 8];
                }
                int krow = kt * 16 + kb;
                #pragma unroll
                for (int nf = 0; nf < 4; nf++) {
                    int pb = wc * 32 + nf * 8 + gid;
                    bfr[nf][0] = Bs[(krow + tig) * BSP + pb];
                    bfr[nf][1] = Bs[(krow + tig + 4) * BSP + pb];
                }
                #pragma unroll
                for (int mf = 0; mf < 2; mf++)
                    #pragma unroll
                    for (int nf = 0; nf < 4; nf++)
                        mma_bf16(d[mf][nf], af[mf], bfr[nf]);
            }
        }
        if (more) {
            *(uint4*)&As[buf ^ 1][ar0 * ASP + ac0] = na0;
            *(uint4*)&As[buf ^ 1][ar1 * ASP + ac0] = na1;
        }
        __syncthreads();

        if (kt == 5) {
            // ---- epilogue for o-tile ot ----
            int o0 = ot * 128;
            if (mode == 0) {
                #pragma unroll
                for (int mf = 0; mf < 2; mf++) {
                    #pragma unroll
                    for (int nf = 0; nf < 4; nf++) {
                        int p = p0 + wc * 32 + nf * 8 + tig * 2;
                        #pragma unroll
                        for (int half = 0; half < 2; half++) {
                            int o = o0 + wr * 32 + mf * 16 + gid + half * 8;
                            float v0 = d[mf][nf][half * 2 + 0];
                            float v1 = d[mf][nf][half * 2 + 1];
                            bool valid = (o < 576);
                            if (valid) {
                                float bia = g_qkvb[o];
                                v0 += bia; v1 += bia;
                                if (o < 192) {      // Q: add scaled prompt (fp16)
                                    __half2 hv = *(const __half2*)
                                        (g_hp + ((size_t)(b * 192 + o)) * HWn + p);
                                    float2 hf = __half22float2(hv);
                                    v0 = fmaf(hf.x, QSCALE, v0);
                                    v1 = fmaf(hf.y, QSCALE, v1);
                                }
                            }
                            float pv0 = __shfl_xor_sync(0xffffffffu, v0, 4);
                            float pv1 = __shfl_xor_sync(0xffffffffu, v1, 4);
                            if (valid) {
                                if (o >= 384) {     // V: fp16
                                    *(__half2*)(g_v + ((size_t)(b * 192 + o - 384)) * HWn + p)
                                        = __floats2half2_rn(v0, v1);
                                } else if ((gid & 1) == 0) {
                                    int o2 = (o < 192) ? (o >> 1) : (96 + ((o - 192) >> 1));
                                    uint2 u;
                                    u.x = packbf(v0, pv0);
                                    u.y = packbf(v1, pv1);
                                    *(uint2*)(g_qk + ((size_t)(b * 192 + o2)) * HWn + p) = u;
                                }
                            }
                        }
                    }
                }
            } else {
                #pragma unroll
                for (int mf = 0; mf < 2; mf++) {
                    int o_lo = o0 + wr * 32 + mf * 16 + gid;
                    #pragma unroll
                    for (int nf = 0; nf < 4; nf++) {
                        int p = p0 + wc * 32 + nf * 8 + tig * 2;
                        #pragma unroll
                        for (int half = 0; half < 2; half++) {
                            int o = o_lo + half * 8;
                            if (o >= 192) continue;
                            float v0 = d[mf][nf][half * 2 + 0];
                            float v1 = d[mf][nf][half * 2 + 1];
                            size_t xo = ((size_t)(b * Cn + o)) * HWn + p;
                            float wchan = g_w1[b * Cn + o];
                            float2 w2p = *(const float2*)(g_w2 + (size_t)b * HWn + p);
                            float2 xv = *(const float2*)(x_in + xo);
                            float pb = projb[o];
                            *(float2*)(dout + xo) = make_float2(v0 + pb + xv.x * wchan * w2p.x,
                                                                v1 + pb + xv.y * wchan * w2p.y);
                        }
                    }
                }
            }
        }
    }
}

// ---------------- depthwise 5x5 reflect conv on fp16 V -> g_sum ---------------
__global__ __launch_bounds__(256) void k_dw(const float* __restrict__ dww, const float* __restrict__ dwb) {
    __shared__ float tile[36 * 36];
    __shared__ float wv[25];
    int tid = threadIdx.x;
    int bc = blockIdx.z;
    int c = bc % Cn;
    int w0 = blockIdx.x * 32, h0 = blockIdx.y * 32;
    const __half* V = g_v + (size_t)bc * HWn;
    if (tid < 25) wv[tid] = dww[c * 25 + tid];
    for (int idx = tid; idx < 36 * 36; idx += 256) {
        int r = idx / 36, cc = idx - r * 36;
        int gy = h0 + r - 2;  if (gy < 0) gy = -gy;  if (gy > 255) gy = 510 - gy;
        int gx = w0 + cc - 2; if (gx < 0) gx = -gx;  if (gx > 255) gx = 510 - gx;
        tile[idx] = __half2float(V[gy * 256 + gx]);
    }
    __syncthreads();
    int tx = tid & 31, ty0 = (tid >> 5) * 4;
    float bias = dwb[c];
    #pragma unroll
    for (int i = 0; i < 4; i++) {
        int ry = ty0 + i;
        float acc = 0.f;
        #pragma unroll
        for (int dy = 0; dy < 5; dy++)
            #pragma unroll
            for (int dx = 0; dx < 5; dx++)
                acc = fmaf(tile[(ry + dy) * 36 + tx + dx], wv[dy * 5 + dx], acc);
        g_sum[(size_t)bc * HWn + (h0 + ry) * 256 + w0 + tx] = acc + bias;
    }
}

// ---------------- tensor-core window attention --------------------------------
#define QP 20
#define VP 36
__global__ __launch_bounds__(64) void k_attn() {
    __shared__ uint32_t qpk[64 * QP];
    __shared__ uint32_t kpk[64 * QP];
    __shared__ uint32_t vpk[32 * VP];
    int bid = blockIdx.x;
    int h = bid % NHn; int win = bid / NHn;
    int wx = win & 31, wy = (win >> 5) & 31, b = win >> 10;
    int tid = threadIdx.x, lane = tid & 31, w = tid >> 5;
    int gid = lane >> 2, tig = lane & 3;
    int ch0 = h * HDn, q2 = h * 16;
    size_t pbase = (size_t)(wy * 8) * 256 + wx * 8;

    // stage Q,K: direct channel-paired uint32 loads
    {
        int t = tid;
        size_t po = pbase + (t >> 3) * 256 + (t & 7);
        const uint32_t* qb = g_qk + (size_t)(b * 192) * HWn + po;
        #pragma unroll
        for (int i = 0; i < 16; i++) {
            qpk[t * QP + i] = qb[(size_t)(q2 + i) * HWn];
            kpk[t * QP + i] = qb[(size_t)(96 + q2 + i) * HWn];
        }
    }
    // stage V: token-paired from fp16 (adjacent tokens = one half2)
    for (int idx = tid; idx < 32 * 32; idx += 64) {
        int dd = idx >> 5, t2 = idx & 31;
        int t = t2 * 2;
        size_t po = pbase + (t >> 3) * 256 + (t & 7);
        float2 vv = __half22float2(*(const __half2*)
            (g_v + ((size_t)(b * 192 + ch0 + dd)) * HWn + po));
        vpk[dd * VP + t2] = packbf(vv.x, vv.y);
    }
    __syncthreads();

    // S = Q K^T  (each warp: rows 32w..32w+31)
    float sf[2][8][4];
    #pragma unroll
    for (int mt = 0; mt < 2; mt++)
        #pragma unroll
        for (int nt = 0; nt < 8; nt++)
            #pragma unroll
            for (int r = 0; r < 4; r++) sf[mt][nt][r] = 0.f;
    int mrow = w * 32;
    #pragma unroll
    for (int s = 0; s < 2; s++) {
        uint32_t af[2][4];
        #pragma unroll
        for (int mt = 0; mt < 2; mt++) {
            int rb = (mrow + mt * 16 + gid) * QP + s * 8;
            af[mt][0] = qpk[rb + tig];
            af[mt][1] = qpk[rb + 8 * QP + tig];
            af[mt][2] = qpk[rb + tig + 4];
            af[mt][3] = qpk[rb + 8 * QP + tig + 4];
        }
        #pragma unroll
        for (int nt = 0; nt < 8; nt++) {
            uint32_t bfr[2];
            int rb = (nt * 8 + gid) * QP + s * 8;
            bfr[0] = kpk[rb + tig];
            bfr[1] = kpk[rb + tig + 4];
            #pragma unroll
            for (int mt = 0; mt < 2; mt++)
                mma_bf16(sf[mt][nt], af[mt], bfr);
        }
    }

    // bias + softmax (rows live in 4-lane quads)
    float den[2][2];
    #pragma unroll
    for (int mt = 0; mt < 2; mt++) {
        #pragma unroll
        for (int rh = 0; rh < 2; rh++) {
            int irow = mrow + mt * 16 + rh * 8 + gid;
            const float* br = g_biasT + h * 4096 + irow * 64 + tig * 2;
            float mx = -1e30f;
            #pragma unroll
            for (int nt = 0; nt < 8; nt++) {
                float2 bb = *(const float2*)(br + nt * 8);
                float s0 = sf[mt][nt][rh * 2 + 0] + bb.x;
                float s1 = sf[mt][nt][rh * 2 + 1] + bb.y;
                sf[mt][nt][rh * 2 + 0] = s0;
                sf[mt][nt][rh * 2 + 1] = s1;
                mx = fmaxf(mx, fmaxf(s0, s1));
            }
            mx = fmaxf(mx, __shfl_xor_sync(0xffffffffu, mx, 1));
            mx = fmaxf(mx, __shfl_xor_sync(0xffffffffu, mx, 2));
            float ds = 0.f;
            #pragma unroll
            for (int nt = 0; nt < 8; nt++) {
                float e0 = __expf(sf[mt][nt][rh * 2 + 0] - mx);
                float e1 = __expf(sf[mt][nt][rh * 2 + 1] - mx);
                sf[mt][nt][rh * 2 + 0] = e0;
                sf[mt][nt][rh * 2 + 1] = e1;
                ds += e0 + e1;
            }
            ds += __shfl_xor_sync(0xffffffffu, ds, 1);
            ds += __shfl_xor_sync(0xffffffffu, ds, 2);
            den[mt][rh] = ds;
        }
    }

    // repack P as A-fragments
    uint32_t apv[2][4][4];
    #pragma unroll
    for (int mt = 0; mt < 2; mt++)
        #pragma unroll
        for (int kt = 0; kt < 4; kt++) {
            apv[mt][kt][0] = packbf(sf[mt][2 * kt][0],     sf[mt][2 * kt][1]);
            apv[mt][kt][1] = packbf(sf[mt][2 * kt][2],     sf[mt][2 * kt][3]);
            apv[mt][kt][2] = packbf(sf[mt][2 * kt + 1][0], sf[mt][2 * kt + 1][1]);
            apv[mt][kt][3] = packbf(sf[mt][2 * kt + 1][2], sf[mt][2 * kt + 1][3]);
        }

    // O = P V
    float of[2][4][4];
    #pragma unroll
    for (int mt = 0; mt < 2; mt++)
        #pragma unroll
        for (int vn = 0; vn < 4; vn++)
            #pragma unroll
            for (int r = 0; r < 4; r++) of[mt][vn][r] = 0.f;
    #pragma unroll
    for (int kt = 0; kt < 4; kt++) {
        uint32_t bfr[4][2];
        #pragma unroll
        for (int vn = 0; vn < 4; vn++) {
            int rb = (vn * 8 + gid) * VP + kt * 8;
            bfr[vn][0] = vpk[rb + tig];
            bfr[vn][1] = vpk[rb + tig + 4];
        }
        #pragma unroll
        for (int mt = 0; mt < 2; mt++)
            #pragma unroll
            for (int vn = 0; vn < 4; vn++)
                mma_bf16(of[mt][vn], apv[mt][kt], bfr[vn]);
    }

    // write: g_attn = O / den  (pure stores, no RMW)
    #pragma unroll
    for (int mt = 0; mt < 2; mt++)
        #pragma unroll
        for (int rh = 0; rh < 2; rh++) {
            int irow = mrow + mt * 16 + rh * 8 + gid;
            size_t po = pbase + (irow >> 3) * 256 + (irow & 7);
            float inv = 1.0f / den[mt][rh];
            #pragma unroll
            for (int vn = 0; vn < 4; vn++) {
                int dd = vn * 8 + tig * 2;
                float* gp = g_attn + ((size_t)(b * 192 + ch0 + dd)) * HWn + po;
                gp[0]   = of[mt][vn][rh * 2 + 0] * inv;
                gp[HWn] = of[mt][vn][rh * 2 + 1] * inv;
            }
        }
}

// ------------------------------ launch ---------------------------------------
extern "C" void kernel_launch(void* const* d_in, const int* in_sizes, int n_in,
                              void* d_out, int out_size) {
    const float* x      = (const float*)d_in[0];
    const float* ln_w   = (const float*)d_in[1];
    const float* ln_b   = (const float*)d_in[2];
    const float* ca_w1  = (const float*)d_in[3];
    const float* ca_w2  = (const float*)d_in[4];
    const float* sa_w3  = (const float*)d_in[5];
    const float* sa_w5  = (const float*)d_in[6];
    const float* sa_w7  = (const float*)d_in[7];
    const float* q_w    = (const float*)d_in[8];
    const float* q_b    = (const float*)d_in[9];
    const float* k_w    = (const float*)d_in[10];
    const float* k_b    = (const float*)d_in[11];
    const float* v_w    = (const float*)d_in[12];
    const float* v_b    = (const float*)d_in[13];
    const float* proj_w = (const float*)d_in[14];
    const float* proj_b = (const float*)d_in[15];
    const float* m_w1   = (const float*)d_in[16];
    const float* m_b1   = (const float*)d_in[17];
    const float* m_w2   = (const float*)d_in[18];
    const float* m_b2   = (const float*)d_in[19];
    const float* dw_w   = (const float*)d_in[20];
    const float* dw_b   = (const float*)d_in[21];
    float* out = (float*)d_out;

    k_setup<<<1, 256>>>(sa_w3, sa_w5, sa_w7);
    k_bias<<<64, 64>>>(m_w1, m_b1, m_w2, m_b2);
    k_pack<<<240, 256>>>(q_w, q_b, k_w, k_b, v_w, v_b, proj_w);

    k_pass12<<<dim3(8, 4, Bn * Cn), 256>>>(x);
    k_hpstats<<<128, 256>>>();
    k_chanattn<<<1, 256>>>(ca_w1, ca_w2);
    k_spatattn<<<(Bn * HWn) / 256, 256>>>();

    k_gemm_bf<<<dim3(HWn / 64, 1, Bn), 256>>>(0, x, nullptr, nullptr, ln_w, ln_b);
    k_dw<<<dim3(Wn / 32, Hn / 32, Bn * Cn), 256>>>(dw_w, dw_b);
    k_attn<<<Bn * 32 * 32 * NHn, 64>>>();
    k_gemm_bf<<<dim3(HWn / 64, 1, Bn), 256>>>(1, x, proj_b, out, nullptr, nullptr);
}